// round 10
// baseline (speedup 1.0000x reference)
#include <cuda_runtime.h>
#include <cuda_bf16.h>
#include <cstdint>

// ---------------------------------------------------------------------------
// Problem constants
// ---------------------------------------------------------------------------
#define BB 2
#define SS 2048
#define DD 1024
#define HH 16
#define RR 64
#define BH (BB * HH)   // 32
#define NEL (BB * SS * DD)

// ---------------------------------------------------------------------------
// mma.sync helpers (baseline PTX, plain sm_100 target)
// ---------------------------------------------------------------------------
__device__ __forceinline__ uint32_t smem_u32(const void* p) {
    uint32_t a;
    asm("{ .reg .u64 t; cvta.to.shared.u64 t, %1; cvt.u32.u64 %0, t; }"
        : "=r"(a) : "l"(p));
    return a;
}
__device__ __forceinline__ void ldm_x4(uint32_t* r, uint32_t addr) {
    asm volatile("ldmatrix.sync.aligned.m8n8.x4.shared.b16 {%0,%1,%2,%3}, [%4];"
                 : "=r"(r[0]), "=r"(r[1]), "=r"(r[2]), "=r"(r[3]) : "r"(addr));
}
__device__ __forceinline__ void ldm_x4_t(uint32_t* r, uint32_t addr) {
    asm volatile("ldmatrix.sync.aligned.m8n8.x4.trans.shared.b16 {%0,%1,%2,%3}, [%4];"
                 : "=r"(r[0]), "=r"(r[1]), "=r"(r[2]), "=r"(r[3]) : "r"(addr));
}
__device__ __forceinline__ void mma_bf16(float* c, const uint32_t* a,
                                         const uint32_t* b) {
    asm volatile(
        "mma.sync.aligned.m16n8k16.row.col.f32.bf16.bf16.f32 "
        "{%0,%1,%2,%3}, {%4,%5,%6,%7}, {%8,%9}, {%0,%1,%2,%3};"
        : "+f"(c[0]), "+f"(c[1]), "+f"(c[2]), "+f"(c[3])
        : "r"(a[0]), "r"(a[1]), "r"(a[2]), "r"(a[3]), "r"(b[0]), "r"(b[1]));
}
__device__ __forceinline__ void cp16(uint32_t dst, const void* src) {
    asm volatile("cp.async.cg.shared.global [%0], [%1], 16;"
                 :: "r"(dst), "l"(__cvta_generic_to_global(src)));
}
#define CP_COMMIT() asm volatile("cp.async.commit_group;" ::: "memory")
#define CP_WAIT0()  asm volatile("cp.async.wait_group 0;" ::: "memory")
#define CP_WAIT1()  asm volatile("cp.async.wait_group 1;" ::: "memory")

__device__ __forceinline__ uint32_t swz(uint32_t o) { return o ^ ((o >> 3) & 0x70); }

// Split a float pair into bf16 hi/lo packed u32s.
// Fast path: packed cvt + (bf16->f32 == shift) identity. Rounding identical
// to __float2bfloat16 (rn).
__device__ __forceinline__ void splitpair(float x, float y,
                                          uint32_t& h, uint32_t& l) {
    asm("cvt.rn.bf16x2.f32 %0, %1, %2;" : "=r"(h) : "f"(y), "f"(x));
    float hx = __uint_as_float(h << 16);
    float hy = __uint_as_float(h & 0xFFFF0000u);
    asm("cvt.rn.bf16x2.f32 %0, %1, %2;" : "=r"(l) : "f"(y - hy), "f"(x - hx));
}

// ---------------------------------------------------------------------------
// Scratch
// ---------------------------------------------------------------------------
__device__ __nv_bfloat16 g_qs[2][NEL];
__device__ __nv_bfloat16 g_ks[2][NEL];
__device__ __nv_bfloat16 g_vs[2][NEL];
__device__ __nv_bfloat16 g_os[2][NEL];          // attn output splits
__device__ __nv_bfloat16 g_wqT[2][DD * DD];
__device__ __nv_bfloat16 g_wkT[2][DD * DD];
__device__ __nv_bfloat16 g_wvT[2][DD * DD];
__device__ __nv_bfloat16 g_woT[2][DD * DD];
// projection outputs as bf16 hi/lo planes, [b,h,s,r] layout
// (Q pre-scaled by 0.125*log2e -> softmax runs in exp2 domain)
__device__ __nv_bfloat16 g_Qb[2][BH * SS * RR];
__device__ __nv_bfloat16 g_Kb[2][BH * SS * RR];
__device__ __nv_bfloat16 g_Vb[2][BH * SS * RR];

// ---------------------------------------------------------------------------
// fp32 -> 2-way bf16 split converter (q/k/v fused via blockIdx.y)
// ---------------------------------------------------------------------------
__global__ void __launch_bounds__(256) conv_rows_kernel(
    const float* __restrict__ q, const float* __restrict__ k,
    const float* __restrict__ v)
{
    const int sel = blockIdx.y;
    const float* src = (sel == 0) ? q : (sel == 1) ? k : v;
    __nv_bfloat16 *d0, *d1;
    if (sel == 0)      { d0 = g_qs[0]; d1 = g_qs[1]; }
    else if (sel == 1) { d0 = g_ks[0]; d1 = g_ks[1]; }
    else               { d0 = g_vs[0]; d1 = g_vs[1]; }

    for (int i = (blockIdx.x * blockDim.x + threadIdx.x) * 4; i < NEL;
         i += gridDim.x * blockDim.x * 4) {
        float4 x = *reinterpret_cast<const float4*>(src + i);
        uint32_t h0, l0, h1, l1;
        splitpair(x.x, x.y, h0, l0);
        splitpair(x.z, x.w, h1, l1);
        *reinterpret_cast<uint2*>(d0 + i) = make_uint2(h0, h1);
        *reinterpret_cast<uint2*>(d1 + i) = make_uint2(l0, l1);
    }
}

__global__ void __launch_bounds__(256) conv_w_kernel(
    const float* __restrict__ wq, const float* __restrict__ wk,
    const float* __restrict__ wv, const float* __restrict__ wo)
{
    const int sel = blockIdx.z;
    const float* W = (sel == 0) ? wq : (sel == 1) ? wk : (sel == 2) ? wv : wo;
    __nv_bfloat16 *d0, *d1;
    if (sel == 0)      { d0 = g_wqT[0]; d1 = g_wqT[1]; }
    else if (sel == 1) { d0 = g_wkT[0]; d1 = g_wkT[1]; }
    else if (sel == 2) { d0 = g_wvT[0]; d1 = g_wvT[1]; }
    else               { d0 = g_woT[0]; d1 = g_woT[1]; }

    __shared__ float tile[32][33];
    const int tx = threadIdx.x & 31;
    const int ty = threadIdx.x >> 5;
    const int ct = blockIdx.x;
    const int rt = blockIdx.y;

    #pragma unroll
    for (int i = 0; i < 4; i++) {
        const int d = rt * 32 + ty + i * 8;
        const int n = ct * 32 + tx;
        size_t idx;
        if (sel < 3) idx = ((size_t)(n >> 6) * DD + d) * RR + (n & 63);
        else         idx = (size_t)d * DD + n;
        tile[ty + i * 8][tx] = W[idx];
    }
    __syncthreads();
    #pragma unroll
    for (int i = 0; i < 4; i++) {
        const int nl = ty + i * 8;
        const int n  = ct * 32 + nl;
        const int d  = rt * 32 + tx;
        float x = tile[tx][nl];
        __nv_bfloat16 b0 = __float2bfloat16(x);
        size_t o = (size_t)n * DD + d;
        d0[o] = b0;
        d1[o] = __float2bfloat16(x - __bfloat162float(b0));
    }
}

// ---------------------------------------------------------------------------
// mma.sync split-bf16 GEMM — 4-plane stages.
//   K-stage 32; combined smem tiles pack [hi 64B | lo 64B] per 128B row, so
//   SW128 swizzle + ldmatrix addressing are unchanged. Per k16: issue the
//   three term products hh + hl + lh. 32 stages (vs 48), -33% tile traffic,
//   -33% ldmatrix, same 64KB smem -> 2 CTAs/SM preserved.
//   kinds 0/1/2 (Q/K/V proj) -> bf16 planes;  kind 3 (out proj) -> fp32.
// ---------------------------------------------------------------------------
#define GEMM_SMEM 65536

__global__ void __launch_bounds__(256) gemm_kernel(float* __restrict__ outC,
                                                   int kind_base)
{
    const int kind = kind_base + blockIdx.z;
    const __nv_bfloat16 *Ax[2], *Bx[2];
    __nv_bfloat16 *P0 = nullptr, *P1 = nullptr;
    float scale = 1.0f;
    if (kind == 0)      { Ax[0] = g_qs[0]; Ax[1] = g_qs[1];
                          Bx[0] = g_wqT[0]; Bx[1] = g_wqT[1];
                          P0 = g_Qb[0]; P1 = g_Qb[1];
                          scale = 0.125f * 1.4426950408889634f; }
    else if (kind == 1) { Ax[0] = g_ks[0]; Ax[1] = g_ks[1];
                          Bx[0] = g_wkT[0]; Bx[1] = g_wkT[1];
                          P0 = g_Kb[0]; P1 = g_Kb[1]; }
    else if (kind == 2) { Ax[0] = g_vs[0]; Ax[1] = g_vs[1];
                          Bx[0] = g_wvT[0]; Bx[1] = g_wvT[1];
                          P0 = g_Vb[0]; P1 = g_Vb[1]; }
    else                { Ax[0] = g_os[0]; Ax[1] = g_os[1];
                          Bx[0] = g_woT[0]; Bx[1] = g_woT[1]; }

    extern __shared__ char smem[];
    const uint32_t sb = smem_u32(smem);
    const int t      = threadIdx.x;
    const int lane   = t & 31;
    const int wid    = t >> 5;
    const int warp_m = wid >> 2;
    const int warp_n = wid & 3;
    const int m0 = blockIdx.y * 128;
    const int n0 = blockIdx.x * 128;

    float acc[4][4][4];
    #pragma unroll
    for (int a = 0; a < 4; a++)
        #pragma unroll
        for (int b = 0; b < 4; b++)
            #pragma unroll
            for (int c = 0; c < 4; c++) acc[a][b][c] = 0.f;

    const int a_row  = warp_m * 64 + (lane & 15);
    const int a_koff = (lane >> 4) * 16;
    const int b_row  = warp_n * 32 + (lane & 7) + ((lane >> 4) & 1) * 8;
    const int b_koff = ((lane >> 3) & 1) * 16;

    // stage loader: combined tiles. chunk c16<4 -> hi plane, c16>=4 -> lo.
    // A tile at base+0, B tile at base+16384. k0 = stage*32 (elements).
    #define GEMM_LOAD_STAGE(base, k0)                                         \
    do {                                                                      \
        _Pragma("unroll")                                                     \
        for (int it = 0; it < 4; it++) {                                      \
            const int cid = it * 256 + t;                                     \
            const int row = cid >> 3, c16 = cid & 7;                          \
            const int pl = c16 >> 2, cc = c16 & 3;                            \
            cp16((base) + swz(row * 128 + c16 * 16),                          \
                 Ax[pl] + (size_t)(m0 + row) * DD + (k0) + cc * 8);           \
            cp16((base) + 16384u + swz(row * 128 + c16 * 16),                 \
                 Bx[pl] + (size_t)(n0 + row) * DD + (k0) + cc * 8);           \
        }                                                                     \
    } while (0)

    GEMM_LOAD_STAGE(sb, 0);
    CP_COMMIT();

    for (int s = 0; s < 32; s++) {
        CP_WAIT0();
        __syncthreads();
        if (s + 1 < 32) {
            GEMM_LOAD_STAGE(sb + ((s + 1) & 1) * 32768u, (s + 1) * 32);
            CP_COMMIT();
        }
        const uint32_t abase = sb + (s & 1) * 32768u;
        const uint32_t bbase = abase + 16384u;
        #pragma unroll
        for (int k16 = 0; k16 < 2; k16++) {
            uint32_t brh[4][2], brl[4][2];
            #pragma unroll
            for (int nb = 0; nb < 2; nb++) {
                const int n = b_row + nb * 16;
                uint32_t r[4];
                ldm_x4(r, bbase + swz(n * 128 + k16 * 32 + b_koff));
                brh[nb * 2][0] = r[0]; brh[nb * 2][1] = r[1];
                brh[nb * 2 + 1][0] = r[2]; brh[nb * 2 + 1][1] = r[3];
                ldm_x4(r, bbase + swz(n * 128 + 64 + k16 * 32 + b_koff));
                brl[nb * 2][0] = r[0]; brl[nb * 2][1] = r[1];
                brl[nb * 2 + 1][0] = r[2]; brl[nb * 2 + 1][1] = r[3];
            }
            #pragma unroll
            for (int mi = 0; mi < 4; mi++) {
                uint32_t arh[4], arl[4];
                const int row = a_row + mi * 16;
                ldm_x4(arh, abase + swz(row * 128 + k16 * 32 + a_koff));
                ldm_x4(arl, abase + swz(row * 128 + 64 + k16 * 32 + a_koff));
                #pragma unroll
                for (int ni = 0; ni < 4; ni++) {
                    mma_bf16(acc[mi][ni], arh, brh[ni]);   // hi*hi
                    mma_bf16(acc[mi][ni], arh, brl[ni]);   // hi*lo
                    mma_bf16(acc[mi][ni], arl, brh[ni]);   // lo*hi
                }
            }
        }
    }
    #undef GEMM_LOAD_STAGE

    // epilogue
    #pragma unroll
    for (int mi = 0; mi < 4; mi++) {
        #pragma unroll
        for (int ni = 0; ni < 4; ni++) {
            const int r0 = m0 + warp_m * 64 + mi * 16 + (lane >> 2);
            const int c  = n0 + warp_n * 32 + ni * 8 + (lane & 3) * 2;
            #pragma unroll
            for (int half = 0; half < 2; half++) {
                const int m = r0 + half * 8;
                float v0 = acc[mi][ni][half * 2] * scale;
                float v1 = acc[mi][ni][half * 2 + 1] * scale;
                if (kind < 3) {
                    const int h = c >> 6, r = c & 63;
                    const int b = m >> 11, sl = m & 2047;
                    size_t idx = (((size_t)b * HH + h) * SS + sl) * RR + r;
                    uint32_t hh, ll;
                    splitpair(v0, v1, hh, ll);
                    *reinterpret_cast<uint32_t*>(&P0[idx]) = hh;
                    *reinterpret_cast<uint32_t*>(&P1[idx]) = ll;
                } else {
                    *reinterpret_cast<float2*>(&outC[(size_t)m * DD + c]) =
                        make_float2(v0, v1);
                }
            }
        }
    }
}

// ---------------------------------------------------------------------------
// Tensor-core flash attention (exp2 domain; logits pre-scaled by log2e).
// ---------------------------------------------------------------------------
#define ATT_SMEM 98304

__global__ void __launch_bounds__(256, 2) attn_kernel()
{
    const int z  = blockIdx.y;
    const int s0 = blockIdx.x * 128;
    extern __shared__ char sm[];
    const uint32_t sb = smem_u32(sm);
    const int t = threadIdx.x, lane = t & 31, wid = t >> 5;
    const size_t zoff = (size_t)z * SS * RR;

    #define QOFF(p)      (sb + (p) * 16384u)
    #define KOFF(bf, p)  (sb + 32768u + (bf) * 32768u + (p) * 8192u)
    #define VOFF(bf, p)  (sb + 32768u + (bf) * 32768u + 16384u + (p) * 8192u)

    #pragma unroll
    for (int p = 0; p < 2; p++) {
        const __nv_bfloat16* src = g_Qb[p] + zoff + (size_t)s0 * RR;
        #pragma unroll
        for (int it = 0; it < 4; it++) {
            const int cid = it * 256 + t;
            const int row = cid >> 3, c16 = cid & 7;
            cp16(QOFF(p) + swz(row * 128 + c16 * 16), src + row * 64 + c16 * 8);
        }
    }
    #pragma unroll
    for (int p = 0; p < 2; p++) {
        #pragma unroll
        for (int it = 0; it < 2; it++) {
            const int cid = it * 256 + t;
            const int row = cid >> 3, c16 = cid & 7;
            cp16(KOFF(0, p) + swz(row * 128 + c16 * 16),
                 g_Kb[p] + zoff + (size_t)row * RR + c16 * 8);
            cp16(VOFF(0, p) + swz(row * 128 + c16 * 16),
                 g_Vb[p] + zoff + (size_t)row * RR + c16 * 8);
        }
    }
    CP_COMMIT();

    float m0r = -3.0e38f, m1r = -3.0e38f, l0r = 0.f, l1r = 0.f;
    float oa[8][4];
    #pragma unroll
    for (int b = 0; b < 8; b++)
        #pragma unroll
        for (int c = 0; c < 4; c++) oa[b][c] = 0.f;

    for (int s = 0; s < 32; s++) {
        const int buf = s & 1;
        if (s + 1 < 32) {
            const int nb = (s + 1) & 1;
            const int kv = (s + 1) * 64;
            #pragma unroll
            for (int p = 0; p < 2; p++) {
                #pragma unroll
                for (int it = 0; it < 2; it++) {
                    const int cid = it * 256 + t;
                    const int row = cid >> 3, c16 = cid & 7;
                    cp16(KOFF(nb, p) + swz(row * 128 + c16 * 16),
                         g_Kb[p] + zoff + (size_t)(kv + row) * RR + c16 * 8);
                    cp16(VOFF(nb, p) + swz(row * 128 + c16 * 16),
                         g_Vb[p] + zoff + (size_t)(kv + row) * RR + c16 * 8);
                }
            }
            CP_COMMIT();
            CP_WAIT1();
        } else {
            CP_WAIT0();
        }
        __syncthreads();

        // ---- GEMM1: S = Q K^T (3 split terms) ----
        float sa[8][4];
        #pragma unroll
        for (int b = 0; b < 8; b++)
            #pragma unroll
            for (int c = 0; c < 4; c++) sa[b][c] = 0.f;

        #pragma unroll
        for (int kb = 0; kb < 4; kb++) {
            uint32_t aq[2][4];
            const int arow = wid * 16 + (lane & 15);
            const int akoff = kb * 32 + (lane >> 4) * 16;
            #pragma unroll
            for (int p = 0; p < 2; p++)
                ldm_x4(aq[p], QOFF(p) + swz(arow * 128 + akoff));
            #pragma unroll
            for (int g = 0; g < 4; g++) {
                uint32_t bk[2][4];
                const int brow = g * 16 + (lane & 7) + ((lane >> 4) & 1) * 8;
                const int bkoff = kb * 32 + ((lane >> 3) & 1) * 16;
                #pragma unroll
                for (int p = 0; p < 2; p++)
                    ldm_x4(bk[p], KOFF(buf, p) + swz(brow * 128 + bkoff));
                mma_bf16(sa[2 * g],     aq[0], &bk[0][0]);   // hi*hi
                mma_bf16(sa[2 * g + 1], aq[0], &bk[0][2]);
                mma_bf16(sa[2 * g],     aq[0], &bk[1][0]);   // hi*lo
                mma_bf16(sa[2 * g + 1], aq[0], &bk[1][2]);
                mma_bf16(sa[2 * g],     aq[1], &bk[0][0]);   // lo*hi
                mma_bf16(sa[2 * g + 1], aq[1], &bk[0][2]);
            }
        }

        // ---- online softmax (exp2 domain) ----
        float mt0 = -3.0e38f, mt1 = -3.0e38f;
        #pragma unroll
        for (int b = 0; b < 8; b++) {
            mt0 = fmaxf(mt0, fmaxf(sa[b][0], sa[b][1]));
            mt1 = fmaxf(mt1, fmaxf(sa[b][2], sa[b][3]));
        }
        mt0 = fmaxf(mt0, __shfl_xor_sync(0xffffffffu, mt0, 1));
        mt0 = fmaxf(mt0, __shfl_xor_sync(0xffffffffu, mt0, 2));
        mt1 = fmaxf(mt1, __shfl_xor_sync(0xffffffffu, mt1, 1));
        mt1 = fmaxf(mt1, __shfl_xor_sync(0xffffffffu, mt1, 2));
        const float mn0 = fmaxf(m0r, mt0), mn1 = fmaxf(m1r, mt1);
        const float al0 = exp2f(m0r - mn0), al1 = exp2f(m1r - mn1);
        m0r = mn0; m1r = mn1;
        float rs0 = 0.f, rs1 = 0.f;
        #pragma unroll
        for (int b = 0; b < 8; b++) {
            sa[b][0] = exp2f(sa[b][0] - mn0);
            sa[b][1] = exp2f(sa[b][1] - mn0);
            sa[b][2] = exp2f(sa[b][2] - mn1);
            sa[b][3] = exp2f(sa[b][3] - mn1);
            rs0 += sa[b][0] + sa[b][1];
            rs1 += sa[b][2] + sa[b][3];
        }
        rs0 += __shfl_xor_sync(0xffffffffu, rs0, 1);
        rs0 += __shfl_xor_sync(0xffffffffu, rs0, 2);
        rs1 += __shfl_xor_sync(0xffffffffu, rs1, 1);
        rs1 += __shfl_xor_sync(0xffffffffu, rs1, 2);
        l0r = l0r * al0 + rs0;
        l1r = l1r * al1 + rs1;
        #pragma unroll
        for (int b = 0; b < 8; b++) {
            oa[b][0] *= al0; oa[b][1] *= al0;
            oa[b][2] *= al1; oa[b][3] *= al1;
        }

        // ---- GEMM2: O += P V (3 split terms) ----
        #pragma unroll
        for (int kb = 0; kb < 4; kb++) {
            uint32_t ph[4], pl[4];
            splitpair(sa[2 * kb][0],     sa[2 * kb][1],     ph[0], pl[0]);
            splitpair(sa[2 * kb][2],     sa[2 * kb][3],     ph[1], pl[1]);
            splitpair(sa[2 * kb + 1][0], sa[2 * kb + 1][1], ph[2], pl[2]);
            splitpair(sa[2 * kb + 1][2], sa[2 * kb + 1][3], ph[3], pl[3]);
            #pragma unroll
            for (int g = 0; g < 4; g++) {
                uint32_t bv[2][4];
                const int trow = kb * 16 + (lane & 7) + ((lane >> 3) & 1) * 8;
                const int rbyte = g * 32 + ((lane >> 4) & 1) * 16;
                #pragma unroll
                for (int p = 0; p < 2; p++)
                    ldm_x4_t(bv[p], VOFF(buf, p) + swz(trow * 128 + rbyte));
                mma_bf16(oa[2 * g], ph, &bv[0][0]);
                mma_bf16(oa[2 * g], ph, &bv[1][0]);
                mma_bf16(oa[2 * g], pl, &bv[0][0]);
                mma_bf16(oa[2 * g + 1], ph, &bv[0][2]);
                mma_bf16(oa[2 * g + 1], ph, &bv[1][2]);
                mma_bf16(oa[2 * g + 1], pl, &bv[0][2]);
            }
        }
        __syncthreads();
    }

    // ---- epilogue ----
    const float i0 = 1.0f / l0r, i1 = 1.0f / l1r;
    #pragma unroll
    for (int b = 0; b < 8; b++) {
        const int r   = b * 8 + (lane & 3) * 2;
        const int r0w = s0 + wid * 16 + (lane >> 2);
        uint32_t hh, ll;
        size_t idx = zoff + (size_t)r0w * RR + r;
        splitpair(oa[b][0] * i0, oa[b][1] * i0, hh, ll);
        *reinterpret_cast<uint32_t*>(&g_os[0][idx]) = hh;
        *reinterpret_cast<uint32_t*>(&g_os[1][idx]) = ll;
        idx = zoff + (size_t)(r0w + 8) * RR + r;
        splitpair(oa[b][2] * i1, oa[b][3] * i1, hh, ll);
        *reinterpret_cast<uint32_t*>(&g_os[0][idx]) = hh;
        *reinterpret_cast<uint32_t*>(&g_os[1][idx]) = ll;
    }
    #undef QOFF
    #undef KOFF
    #undef VOFF
}

// ---------------------------------------------------------------------------
// Launch
// ---------------------------------------------------------------------------
extern "C" void kernel_launch(void* const* d_in, const int* in_sizes, int n_in,
                              void* d_out, int out_size)
{
    const float* q  = (const float*)d_in[0];
    const float* k  = (const float*)d_in[1];
    const float* v  = (const float*)d_in[2];
    const float* wq = (const float*)d_in[3];
    const float* wk = (const float*)d_in[4];
    const float* wv = (const float*)d_in[5];
    const float* wo = (const float*)d_in[6];
    float* out = (float*)d_out;

    (void)in_sizes; (void)n_in; (void)out_size;

    cudaFuncSetAttribute(gemm_kernel,
                         cudaFuncAttributeMaxDynamicSharedMemorySize, GEMM_SMEM);
    cudaFuncSetAttribute(attn_kernel,
                         cudaFuncAttributeMaxDynamicSharedMemorySize, ATT_SMEM);

    // 1) split inputs + weights to bf16 hi/lo
    conv_rows_kernel<<<dim3(1024, 3), 256>>>(q, k, v);
    conv_w_kernel<<<dim3(32, 32, 4), 256>>>(wq, wk, wv, wo);

    // 2) Q/K/V projections -> bf16 planes (Q pre-scaled by log2e/8)
    gemm_kernel<<<dim3(8, 32, 3), 256, GEMM_SMEM>>>(nullptr, 0);

    // 3) tensor-core flash attention -> g_os planes
    attn_kernel<<<dim3(16, 32), 256, ATT_SMEM>>>();

    // 4) output projection -> fp32 out
    gemm_kernel<<<dim3(8, 32, 1), 256, GEMM_SMEM>>>(out, 3);
}

// round 11
// speedup vs baseline: 1.0654x; 1.0654x over previous
#include <cuda_runtime.h>
#include <cuda_bf16.h>
#include <cstdint>

// ---------------------------------------------------------------------------
// Problem constants
// ---------------------------------------------------------------------------
#define BB 2
#define SS 2048
#define DD 1024
#define HH 16
#define RR 64
#define BH (BB * HH)   // 32
#define NEL (BB * SS * DD)

// ---------------------------------------------------------------------------
// mma.sync helpers (baseline PTX, plain sm_100 target)
// ---------------------------------------------------------------------------
__device__ __forceinline__ uint32_t smem_u32(const void* p) {
    uint32_t a;
    asm("{ .reg .u64 t; cvta.to.shared.u64 t, %1; cvt.u32.u64 %0, t; }"
        : "=r"(a) : "l"(p));
    return a;
}
__device__ __forceinline__ void ldm_x4(uint32_t* r, uint32_t addr) {
    asm volatile("ldmatrix.sync.aligned.m8n8.x4.shared.b16 {%0,%1,%2,%3}, [%4];"
                 : "=r"(r[0]), "=r"(r[1]), "=r"(r[2]), "=r"(r[3]) : "r"(addr));
}
__device__ __forceinline__ void ldm_x4_t(uint32_t* r, uint32_t addr) {
    asm volatile("ldmatrix.sync.aligned.m8n8.x4.trans.shared.b16 {%0,%1,%2,%3}, [%4];"
                 : "=r"(r[0]), "=r"(r[1]), "=r"(r[2]), "=r"(r[3]) : "r"(addr));
}
__device__ __forceinline__ void mma_bf16(float* c, const uint32_t* a,
                                         const uint32_t* b) {
    asm volatile(
        "mma.sync.aligned.m16n8k16.row.col.f32.bf16.bf16.f32 "
        "{%0,%1,%2,%3}, {%4,%5,%6,%7}, {%8,%9}, {%0,%1,%2,%3};"
        : "+f"(c[0]), "+f"(c[1]), "+f"(c[2]), "+f"(c[3])
        : "r"(a[0]), "r"(a[1]), "r"(a[2]), "r"(a[3]), "r"(b[0]), "r"(b[1]));
}
__device__ __forceinline__ void cp16(uint32_t dst, const void* src) {
    asm volatile("cp.async.cg.shared.global [%0], [%1], 16;"
                 :: "r"(dst), "l"(__cvta_generic_to_global(src)));
}
#define CP_COMMIT() asm volatile("cp.async.commit_group;" ::: "memory")
#define CP_WAIT0()  asm volatile("cp.async.wait_group 0;" ::: "memory")

__device__ __forceinline__ uint32_t swz(uint32_t o) { return o ^ ((o >> 3) & 0x70); }

// Split a float pair into bf16 hi/lo packed u32s (rn rounding, fast path).
__device__ __forceinline__ void splitpair(float x, float y,
                                          uint32_t& h, uint32_t& l) {
    asm("cvt.rn.bf16x2.f32 %0, %1, %2;" : "=r"(h) : "f"(y), "f"(x));
    float hx = __uint_as_float(h << 16);
    float hy = __uint_as_float(h & 0xFFFF0000u);
    asm("cvt.rn.bf16x2.f32 %0, %1, %2;" : "=r"(l) : "f"(y - hy), "f"(x - hx));
}

// ---------------------------------------------------------------------------
// Scratch
// ---------------------------------------------------------------------------
__device__ __nv_bfloat16 g_qs[2][NEL];
__device__ __nv_bfloat16 g_ks[2][NEL];
__device__ __nv_bfloat16 g_vs[2][NEL];
__device__ __nv_bfloat16 g_os[2][NEL];          // attn output splits
__device__ __nv_bfloat16 g_wqT[2][DD * DD];
__device__ __nv_bfloat16 g_wkT[2][DD * DD];
__device__ __nv_bfloat16 g_wvT[2][DD * DD];
__device__ __nv_bfloat16 g_woT[2][DD * DD];
// projection outputs as bf16 hi/lo planes, [b,h,s,r] layout
// (Q pre-scaled by 0.125*log2e -> softmax runs in exp2 domain)
__device__ __nv_bfloat16 g_Qb[2][BH * SS * RR];
__device__ __nv_bfloat16 g_Kb[2][BH * SS * RR];
__device__ __nv_bfloat16 g_Vb[2][BH * SS * RR];

// ---------------------------------------------------------------------------
// fp32 -> 2-way bf16 split converter (q/k/v fused via blockIdx.y)
// ---------------------------------------------------------------------------
__global__ void __launch_bounds__(256) conv_rows_kernel(
    const float* __restrict__ q, const float* __restrict__ k,
    const float* __restrict__ v)
{
    const int sel = blockIdx.y;
    const float* src = (sel == 0) ? q : (sel == 1) ? k : v;
    __nv_bfloat16 *d0, *d1;
    if (sel == 0)      { d0 = g_qs[0]; d1 = g_qs[1]; }
    else if (sel == 1) { d0 = g_ks[0]; d1 = g_ks[1]; }
    else               { d0 = g_vs[0]; d1 = g_vs[1]; }

    for (int i = (blockIdx.x * blockDim.x + threadIdx.x) * 4; i < NEL;
         i += gridDim.x * blockDim.x * 4) {
        float4 x = *reinterpret_cast<const float4*>(src + i);
        uint32_t h0, l0, h1, l1;
        splitpair(x.x, x.y, h0, l0);
        splitpair(x.z, x.w, h1, l1);
        *reinterpret_cast<uint2*>(d0 + i) = make_uint2(h0, h1);
        *reinterpret_cast<uint2*>(d1 + i) = make_uint2(l0, l1);
    }
}

__global__ void __launch_bounds__(256) conv_w_kernel(
    const float* __restrict__ wq, const float* __restrict__ wk,
    const float* __restrict__ wv, const float* __restrict__ wo)
{
    const int sel = blockIdx.z;
    const float* W = (sel == 0) ? wq : (sel == 1) ? wk : (sel == 2) ? wv : wo;
    __nv_bfloat16 *d0, *d1;
    if (sel == 0)      { d0 = g_wqT[0]; d1 = g_wqT[1]; }
    else if (sel == 1) { d0 = g_wkT[0]; d1 = g_wkT[1]; }
    else if (sel == 2) { d0 = g_wvT[0]; d1 = g_wvT[1]; }
    else               { d0 = g_woT[0]; d1 = g_woT[1]; }

    __shared__ float tile[32][33];
    const int tx = threadIdx.x & 31;
    const int ty = threadIdx.x >> 5;
    const int ct = blockIdx.x;
    const int rt = blockIdx.y;

    #pragma unroll
    for (int i = 0; i < 4; i++) {
        const int d = rt * 32 + ty + i * 8;
        const int n = ct * 32 + tx;
        size_t idx;
        if (sel < 3) idx = ((size_t)(n >> 6) * DD + d) * RR + (n & 63);
        else         idx = (size_t)d * DD + n;
        tile[ty + i * 8][tx] = W[idx];
    }
    __syncthreads();
    #pragma unroll
    for (int i = 0; i < 4; i++) {
        const int nl = ty + i * 8;
        const int n  = ct * 32 + nl;
        const int d  = rt * 32 + tx;
        float x = tile[tx][nl];
        __nv_bfloat16 b0 = __float2bfloat16(x);
        size_t o = (size_t)n * DD + d;
        d0[o] = b0;
        d1[o] = __float2bfloat16(x - __bfloat162float(b0));
    }
}

// ---------------------------------------------------------------------------
// mma.sync split-bf16 GEMM — R9 48-stage schedule (the 651us config).
//   3 terms (hi*hi + hi*lo + lo*hi) folded into the stage stream.
//   kinds 0/1/2 (Q/K/V proj) -> bf16 planes; kind 3 (out proj) -> fp32.
// ---------------------------------------------------------------------------
#define GEMM_SMEM 65536

__global__ void __launch_bounds__(256) gemm_kernel(float* __restrict__ outC,
                                                   int kind_base)
{
    const int kind = kind_base + blockIdx.z;
    const __nv_bfloat16 *Ax[2], *Bx[2];
    __nv_bfloat16 *P0 = nullptr, *P1 = nullptr;
    float scale = 1.0f;
    if (kind == 0)      { Ax[0] = g_qs[0]; Ax[1] = g_qs[1];
                          Bx[0] = g_wqT[0]; Bx[1] = g_wqT[1];
                          P0 = g_Qb[0]; P1 = g_Qb[1];
                          scale = 0.125f * 1.4426950408889634f; }
    else if (kind == 1) { Ax[0] = g_ks[0]; Ax[1] = g_ks[1];
                          Bx[0] = g_wkT[0]; Bx[1] = g_wkT[1];
                          P0 = g_Kb[0]; P1 = g_Kb[1]; }
    else if (kind == 2) { Ax[0] = g_vs[0]; Ax[1] = g_vs[1];
                          Bx[0] = g_wvT[0]; Bx[1] = g_wvT[1];
                          P0 = g_Vb[0]; P1 = g_Vb[1]; }
    else                { Ax[0] = g_os[0]; Ax[1] = g_os[1];
                          Bx[0] = g_woT[0]; Bx[1] = g_woT[1]; }
    const int ti[3] = {0, 0, 1};
    const int tj[3] = {0, 1, 0};
    const int NST = 48;

    extern __shared__ char smem[];
    const uint32_t sb = smem_u32(smem);
    const int t      = threadIdx.x;
    const int lane   = t & 31;
    const int wid    = t >> 5;
    const int warp_m = wid >> 2;
    const int warp_n = wid & 3;
    const int m0 = blockIdx.y * 128;
    const int n0 = blockIdx.x * 128;

    float acc[4][4][4];
    #pragma unroll
    for (int a = 0; a < 4; a++)
        #pragma unroll
        for (int b = 0; b < 4; b++)
            #pragma unroll
            for (int c = 0; c < 4; c++) acc[a][b][c] = 0.f;

    const int a_row  = warp_m * 64 + (lane & 15);
    const int a_koff = (lane >> 4) * 16;
    const int b_row  = warp_n * 32 + (lane & 7) + ((lane >> 4) & 1) * 8;
    const int b_koff = ((lane >> 3) & 1) * 16;

    {
        const __nv_bfloat16* Ag = Ax[0];
        const __nv_bfloat16* Bg = Bx[0];
        const uint32_t abase = sb, bbase = sb + 16384;
        #pragma unroll
        for (int it = 0; it < 4; it++) {
            const int cid = it * 256 + t;
            const int row = cid >> 3, c16 = cid & 7;
            cp16(abase + swz(row * 128 + c16 * 16),
                 Ag + (size_t)(m0 + row) * DD + c16 * 8);
            cp16(bbase + swz(row * 128 + c16 * 16),
                 Bg + (size_t)(n0 + row) * DD + c16 * 8);
        }
        CP_COMMIT();
    }

    for (int s = 0; s < NST; s++) {
        CP_WAIT0();
        __syncthreads();
        if (s + 1 < NST) {
            const int sn = s + 1;
            const int tt = sn >> 4;
            const int k0 = (sn & 15) * 64;
            const __nv_bfloat16* Ag = Ax[ti[tt]];
            const __nv_bfloat16* Bg = Bx[tj[tt]];
            const uint32_t abase = sb + (sn & 1) * 32768;
            const uint32_t bbase = abase + 16384;
            #pragma unroll
            for (int it = 0; it < 4; it++) {
                const int cid = it * 256 + t;
                const int row = cid >> 3, c16 = cid & 7;
                cp16(abase + swz(row * 128 + c16 * 16),
                     Ag + (size_t)(m0 + row) * DD + k0 + c16 * 8);
                cp16(bbase + swz(row * 128 + c16 * 16),
                     Bg + (size_t)(n0 + row) * DD + k0 + c16 * 8);
            }
            CP_COMMIT();
        }
        const uint32_t abase = sb + (s & 1) * 32768;
        const uint32_t bbase = abase + 16384;
        #pragma unroll
        for (int k16 = 0; k16 < 64; k16 += 16) {
            uint32_t ar[4][4], br[4][2];
            #pragma unroll
            for (int mi = 0; mi < 4; mi++) {
                const int row = a_row + mi * 16;
                ldm_x4(ar[mi], abase + swz(row * 128 + k16 * 2 + a_koff));
            }
            #pragma unroll
            for (int nb = 0; nb < 2; nb++) {
                const int n = b_row + nb * 16;
                uint32_t r[4];
                ldm_x4(r, bbase + swz(n * 128 + k16 * 2 + b_koff));
                br[nb * 2][0] = r[0]; br[nb * 2][1] = r[1];
                br[nb * 2 + 1][0] = r[2]; br[nb * 2 + 1][1] = r[3];
            }
            #pragma unroll
            for (int mi = 0; mi < 4; mi++)
                #pragma unroll
                for (int ni = 0; ni < 4; ni++)
                    mma_bf16(acc[mi][ni], ar[mi], br[ni]);
        }
    }

    // epilogue
    #pragma unroll
    for (int mi = 0; mi < 4; mi++) {
        #pragma unroll
        for (int ni = 0; ni < 4; ni++) {
            const int r0 = m0 + warp_m * 64 + mi * 16 + (lane >> 2);
            const int c  = n0 + warp_n * 32 + ni * 8 + (lane & 3) * 2;
            #pragma unroll
            for (int half = 0; half < 2; half++) {
                const int m = r0 + half * 8;
                float v0 = acc[mi][ni][half * 2] * scale;
                float v1 = acc[mi][ni][half * 2 + 1] * scale;
                if (kind < 3) {
                    const int h = c >> 6, r = c & 63;
                    const int b = m >> 11, sl = m & 2047;
                    size_t idx = (((size_t)b * HH + h) * SS + sl) * RR + r;
                    uint32_t hh, ll;
                    splitpair(v0, v1, hh, ll);
                    *reinterpret_cast<uint32_t*>(&P0[idx]) = hh;
                    *reinterpret_cast<uint32_t*>(&P1[idx]) = ll;
                } else {
                    *reinterpret_cast<float2*>(&outC[(size_t)m * DD + c]) =
                        make_float2(v0, v1);
                }
            }
        }
    }
}

// ---------------------------------------------------------------------------
// Tensor-core flash attention (exp2 domain). ONE barrier per stage:
//   wait(buf s) -> sync -> prefetch(s+1) -> compute(s).
// The sync guarantees all warps finished stage s-1 (which read buffer
// (s+1)&1) before any warp's prefetch overwrites it.
// ---------------------------------------------------------------------------
#define ATT_SMEM 98304

__global__ void __launch_bounds__(256, 2) attn_kernel()
{
    const int z  = blockIdx.y;
    const int s0 = blockIdx.x * 128;
    extern __shared__ char sm[];
    const uint32_t sb = smem_u32(sm);
    const int t = threadIdx.x, lane = t & 31, wid = t >> 5;
    const size_t zoff = (size_t)z * SS * RR;

    #define QOFF(p)      (sb + (p) * 16384u)
    #define KOFF(bf, p)  (sb + 32768u + (bf) * 32768u + (p) * 8192u)
    #define VOFF(bf, p)  (sb + 32768u + (bf) * 32768u + 16384u + (p) * 8192u)

    #pragma unroll
    for (int p = 0; p < 2; p++) {
        const __nv_bfloat16* src = g_Qb[p] + zoff + (size_t)s0 * RR;
        #pragma unroll
        for (int it = 0; it < 4; it++) {
            const int cid = it * 256 + t;
            const int row = cid >> 3, c16 = cid & 7;
            cp16(QOFF(p) + swz(row * 128 + c16 * 16), src + row * 64 + c16 * 8);
        }
    }
    #pragma unroll
    for (int p = 0; p < 2; p++) {
        #pragma unroll
        for (int it = 0; it < 2; it++) {
            const int cid = it * 256 + t;
            const int row = cid >> 3, c16 = cid & 7;
            cp16(KOFF(0, p) + swz(row * 128 + c16 * 16),
                 g_Kb[p] + zoff + (size_t)row * RR + c16 * 8);
            cp16(VOFF(0, p) + swz(row * 128 + c16 * 16),
                 g_Vb[p] + zoff + (size_t)row * RR + c16 * 8);
        }
    }
    CP_COMMIT();

    float m0r = -3.0e38f, m1r = -3.0e38f, l0r = 0.f, l1r = 0.f;
    float oa[8][4];
    #pragma unroll
    for (int b = 0; b < 8; b++)
        #pragma unroll
        for (int c = 0; c < 4; c++) oa[b][c] = 0.f;

    for (int s = 0; s < 32; s++) {
        const int buf = s & 1;
        CP_WAIT0();
        __syncthreads();
        if (s + 1 < 32) {
            const int nb = (s + 1) & 1;
            const int kv = (s + 1) * 64;
            #pragma unroll
            for (int p = 0; p < 2; p++) {
                #pragma unroll
                for (int it = 0; it < 2; it++) {
                    const int cid = it * 256 + t;
                    const int row = cid >> 3, c16 = cid & 7;
                    cp16(KOFF(nb, p) + swz(row * 128 + c16 * 16),
                         g_Kb[p] + zoff + (size_t)(kv + row) * RR + c16 * 8);
                    cp16(VOFF(nb, p) + swz(row * 128 + c16 * 16),
                         g_Vb[p] + zoff + (size_t)(kv + row) * RR + c16 * 8);
                }
            }
            CP_COMMIT();
        }

        // ---- GEMM1: S = Q K^T (3 split terms) ----
        float sa[8][4];
        #pragma unroll
        for (int b = 0; b < 8; b++)
            #pragma unroll
            for (int c = 0; c < 4; c++) sa[b][c] = 0.f;

        #pragma unroll
        for (int kb = 0; kb < 4; kb++) {
            uint32_t aq[2][4];
            const int arow = wid * 16 + (lane & 15);
            const int akoff = kb * 32 + (lane >> 4) * 16;
            #pragma unroll
            for (int p = 0; p < 2; p++)
                ldm_x4(aq[p], QOFF(p) + swz(arow * 128 + akoff));
            #pragma unroll
            for (int g = 0; g < 4; g++) {
                uint32_t bk[2][4];
                const int brow = g * 16 + (lane & 7) + ((lane >> 4) & 1) * 8;
                const int bkoff = kb * 32 + ((lane >> 3) & 1) * 16;
                #pragma unroll
                for (int p = 0; p < 2; p++)
                    ldm_x4(bk[p], KOFF(buf, p) + swz(brow * 128 + bkoff));
                mma_bf16(sa[2 * g],     aq[0], &bk[0][0]);   // hi*hi
                mma_bf16(sa[2 * g + 1], aq[0], &bk[0][2]);
                mma_bf16(sa[2 * g],     aq[0], &bk[1][0]);   // hi*lo
                mma_bf16(sa[2 * g + 1], aq[0], &bk[1][2]);
                mma_bf16(sa[2 * g],     aq[1], &bk[0][0]);   // lo*hi
                mma_bf16(sa[2 * g + 1], aq[1], &bk[0][2]);
            }
        }

        // ---- online softmax (exp2 domain) ----
        float mt0 = -3.0e38f, mt1 = -3.0e38f;
        #pragma unroll
        for (int b = 0; b < 8; b++) {
            mt0 = fmaxf(mt0, fmaxf(sa[b][0], sa[b][1]));
            mt1 = fmaxf(mt1, fmaxf(sa[b][2], sa[b][3]));
        }
        mt0 = fmaxf(mt0, __shfl_xor_sync(0xffffffffu, mt0, 1));
        mt0 = fmaxf(mt0, __shfl_xor_sync(0xffffffffu, mt0, 2));
        mt1 = fmaxf(mt1, __shfl_xor_sync(0xffffffffu, mt1, 1));
        mt1 = fmaxf(mt1, __shfl_xor_sync(0xffffffffu, mt1, 2));
        const float mn0 = fmaxf(m0r, mt0), mn1 = fmaxf(m1r, mt1);
        const float al0 = exp2f(m0r - mn0), al1 = exp2f(m1r - mn1);
        m0r = mn0; m1r = mn1;
        float rs0 = 0.f, rs1 = 0.f;
        #pragma unroll
        for (int b = 0; b < 8; b++) {
            sa[b][0] = exp2f(sa[b][0] - mn0);
            sa[b][1] = exp2f(sa[b][1] - mn0);
            sa[b][2] = exp2f(sa[b][2] - mn1);
            sa[b][3] = exp2f(sa[b][3] - mn1);
            rs0 += sa[b][0] + sa[b][1];
            rs1 += sa[b][2] + sa[b][3];
        }
        rs0 += __shfl_xor_sync(0xffffffffu, rs0, 1);
        rs0 += __shfl_xor_sync(0xffffffffu, rs0, 2);
        rs1 += __shfl_xor_sync(0xffffffffu, rs1, 1);
        rs1 += __shfl_xor_sync(0xffffffffu, rs1, 2);
        l0r = l0r * al0 + rs0;
        l1r = l1r * al1 + rs1;
        #pragma unroll
        for (int b = 0; b < 8; b++) {
            oa[b][0] *= al0; oa[b][1] *= al0;
            oa[b][2] *= al1; oa[b][3] *= al1;
        }

        // ---- GEMM2: O += P V (3 split terms) ----
        #pragma unroll
        for (int kb = 0; kb < 4; kb++) {
            uint32_t ph[4], pl[4];
            splitpair(sa[2 * kb][0],     sa[2 * kb][1],     ph[0], pl[0]);
            splitpair(sa[2 * kb][2],     sa[2 * kb][3],     ph[1], pl[1]);
            splitpair(sa[2 * kb + 1][0], sa[2 * kb + 1][1], ph[2], pl[2]);
            splitpair(sa[2 * kb + 1][2], sa[2 * kb + 1][3], ph[3], pl[3]);
            #pragma unroll
            for (int g = 0; g < 4; g++) {
                uint32_t bv[2][4];
                const int trow = kb * 16 + (lane & 7) + ((lane >> 3) & 1) * 8;
                const int rbyte = g * 32 + ((lane >> 4) & 1) * 16;
                #pragma unroll
                for (int p = 0; p < 2; p++)
                    ldm_x4_t(bv[p], VOFF(buf, p) + swz(trow * 128 + rbyte));
                mma_bf16(oa[2 * g], ph, &bv[0][0]);
                mma_bf16(oa[2 * g], ph, &bv[1][0]);
                mma_bf16(oa[2 * g], pl, &bv[0][0]);
                mma_bf16(oa[2 * g + 1], ph, &bv[0][2]);
                mma_bf16(oa[2 * g + 1], ph, &bv[1][2]);
                mma_bf16(oa[2 * g + 1], pl, &bv[0][2]);
            }
        }
    }

    // ---- epilogue ----
    const float i0 = 1.0f / l0r, i1 = 1.0f / l1r;
    #pragma unroll
    for (int b = 0; b < 8; b++) {
        const int r   = b * 8 + (lane & 3) * 2;
        const int r0w = s0 + wid * 16 + (lane >> 2);
        uint32_t hh, ll;
        size_t idx = zoff + (size_t)r0w * RR + r;
        splitpair(oa[b][0] * i0, oa[b][1] * i0, hh, ll);
        *reinterpret_cast<uint32_t*>(&g_os[0][idx]) = hh;
        *reinterpret_cast<uint32_t*>(&g_os[1][idx]) = ll;
        idx = zoff + (size_t)(r0w + 8) * RR + r;
        splitpair(oa[b][2] * i1, oa[b][3] * i1, hh, ll);
        *reinterpret_cast<uint32_t*>(&g_os[0][idx]) = hh;
        *reinterpret_cast<uint32_t*>(&g_os[1][idx]) = ll;
    }
    #undef QOFF
    #undef KOFF
    #undef VOFF
}

// ---------------------------------------------------------------------------
// Launch
// ---------------------------------------------------------------------------
extern "C" void kernel_launch(void* const* d_in, const int* in_sizes, int n_in,
                              void* d_out, int out_size)
{
    const float* q  = (const float*)d_in[0];
    const float* k  = (const float*)d_in[1];
    const float* v  = (const float*)d_in[2];
    const float* wq = (const float*)d_in[3];
    const float* wk = (const float*)d_in[4];
    const float* wv = (const float*)d_in[5];
    const float* wo = (const float*)d_in[6];
    float* out = (float*)d_out;

    (void)in_sizes; (void)n_in; (void)out_size;

    cudaFuncSetAttribute(gemm_kernel,
                         cudaFuncAttributeMaxDynamicSharedMemorySize, GEMM_SMEM);
    cudaFuncSetAttribute(attn_kernel,
                         cudaFuncAttributeMaxDynamicSharedMemorySize, ATT_SMEM);

    // 1) split inputs + weights to bf16 hi/lo
    conv_rows_kernel<<<dim3(1024, 3), 256>>>(q, k, v);
    conv_w_kernel<<<dim3(32, 32, 4), 256>>>(wq, wk, wv, wo);

    // 2) Q/K/V projections -> bf16 planes (Q pre-scaled by log2e/8)
    gemm_kernel<<<dim3(8, 32, 3), 256, GEMM_SMEM>>>(nullptr, 0);

    // 3) tensor-core flash attention -> g_os planes
    attn_kernel<<<dim3(16, 32), 256, ATT_SMEM>>>();

    // 4) output projection -> fp32 out
    gemm_kernel<<<dim3(8, 32, 1), 256, GEMM_SMEM>>>(out, 3);
}

// round 12
// speedup vs baseline: 1.1770x; 1.1048x over previous
#include <cuda_runtime.h>
#include <cuda_bf16.h>
#include <cuda_fp16.h>
#include <cstdint>

// ---------------------------------------------------------------------------
// Problem constants
// ---------------------------------------------------------------------------
#define BB 2
#define SS 2048
#define DD 1024
#define HH 16
#define RR 64
#define BH (BB * HH)   // 32
#define NEL (BB * SS * DD)

// ---------------------------------------------------------------------------
// mma.sync helpers (baseline PTX, plain sm_100 target)
// ---------------------------------------------------------------------------
__device__ __forceinline__ uint32_t smem_u32(const void* p) {
    uint32_t a;
    asm("{ .reg .u64 t; cvta.to.shared.u64 t, %1; cvt.u32.u64 %0, t; }"
        : "=r"(a) : "l"(p));
    return a;
}
__device__ __forceinline__ void ldm_x4(uint32_t* r, uint32_t addr) {
    asm volatile("ldmatrix.sync.aligned.m8n8.x4.shared.b16 {%0,%1,%2,%3}, [%4];"
                 : "=r"(r[0]), "=r"(r[1]), "=r"(r[2]), "=r"(r[3]) : "r"(addr));
}
__device__ __forceinline__ void ldm_x4_t(uint32_t* r, uint32_t addr) {
    asm volatile("ldmatrix.sync.aligned.m8n8.x4.trans.shared.b16 {%0,%1,%2,%3}, [%4];"
                 : "=r"(r[0]), "=r"(r[1]), "=r"(r[2]), "=r"(r[3]) : "r"(addr));
}
__device__ __forceinline__ void mma_bf16(float* c, const uint32_t* a,
                                         const uint32_t* b) {
    asm volatile(
        "mma.sync.aligned.m16n8k16.row.col.f32.bf16.bf16.f32 "
        "{%0,%1,%2,%3}, {%4,%5,%6,%7}, {%8,%9}, {%0,%1,%2,%3};"
        : "+f"(c[0]), "+f"(c[1]), "+f"(c[2]), "+f"(c[3])
        : "r"(a[0]), "r"(a[1]), "r"(a[2]), "r"(a[3]), "r"(b[0]), "r"(b[1]));
}
__device__ __forceinline__ void mma_f16(float* c, const uint32_t* a,
                                        const uint32_t* b) {
    asm volatile(
        "mma.sync.aligned.m16n8k16.row.col.f32.f16.f16.f32 "
        "{%0,%1,%2,%3}, {%4,%5,%6,%7}, {%8,%9}, {%0,%1,%2,%3};"
        : "+f"(c[0]), "+f"(c[1]), "+f"(c[2]), "+f"(c[3])
        : "r"(a[0]), "r"(a[1]), "r"(a[2]), "r"(a[3]), "r"(b[0]), "r"(b[1]));
}
__device__ __forceinline__ void cp16(uint32_t dst, const void* src) {
    asm volatile("cp.async.cg.shared.global [%0], [%1], 16;"
                 :: "r"(dst), "l"(__cvta_generic_to_global(src)));
}
#define CP_COMMIT() asm volatile("cp.async.commit_group;" ::: "memory")
#define CP_WAIT0()  asm volatile("cp.async.wait_group 0;" ::: "memory")

__device__ __forceinline__ uint32_t swz(uint32_t o) { return o ^ ((o >> 3) & 0x70); }

__device__ __forceinline__ float ex2f(float x) {
    float y;
    asm("ex2.approx.ftz.f32 %0, %1;" : "=f"(y) : "f"(x));
    return y;
}
__device__ __forceinline__ float rcpf(float x) {
    float y;
    asm("rcp.approx.ftz.f32 %0, %1;" : "=f"(y) : "f"(x));
    return y;
}

// Split a float pair into bf16 hi/lo packed u32s (rn rounding).
__device__ __forceinline__ void splitpair(float x, float y,
                                          uint32_t& h, uint32_t& l) {
    asm("cvt.rn.bf16x2.f32 %0, %1, %2;" : "=r"(h) : "f"(y), "f"(x));
    float hx = __uint_as_float(h << 16);
    float hy = __uint_as_float(h & 0xFFFF0000u);
    asm("cvt.rn.bf16x2.f32 %0, %1, %2;" : "=r"(l) : "f"(y - hy), "f"(x - hx));
}
// fp16 variant (for the V planes)
__device__ __forceinline__ void splitpair_h(float x, float y,
                                            uint32_t& h, uint32_t& l) {
    __half2 H = __floats2half2_rn(x, y);
    h = *reinterpret_cast<uint32_t*>(&H);
    float2 hf = __half22float2(H);
    __half2 L = __floats2half2_rn(x - hf.x, y - hf.y);
    l = *reinterpret_cast<uint32_t*>(&L);
}
// pack two floats to fp16x2
__device__ __forceinline__ uint32_t packh2(float x, float y) {
    __half2 H = __floats2half2_rn(x, y);
    return *reinterpret_cast<uint32_t*>(&H);
}

// ---------------------------------------------------------------------------
// Scratch
// ---------------------------------------------------------------------------
__device__ __nv_bfloat16 g_qs[2][NEL];
__device__ __nv_bfloat16 g_ks[2][NEL];
__device__ __nv_bfloat16 g_vs[2][NEL];
__device__ __nv_bfloat16 g_os[2][NEL];          // attn output splits (bf16)
__device__ __nv_bfloat16 g_wqT[2][DD * DD];
__device__ __nv_bfloat16 g_wkT[2][DD * DD];
__device__ __nv_bfloat16 g_wvT[2][DD * DD];
__device__ __nv_bfloat16 g_woT[2][DD * DD];
// projection outputs, [b,h,s,r] layout:
//   Q/K as bf16 hi/lo planes (Q pre-scaled by 0.125*log2e, exp2 domain)
//   V as fp16 hi/lo planes (consumed by fp16 PV mma)
__device__ __nv_bfloat16 g_Qb[2][BH * SS * RR];
__device__ __nv_bfloat16 g_Kb[2][BH * SS * RR];
__device__ __half        g_Vh[2][BH * SS * RR];

// ---------------------------------------------------------------------------
// fp32 -> 2-way bf16 split converter (q/k/v fused via blockIdx.y)
// ---------------------------------------------------------------------------
__global__ void __launch_bounds__(256) conv_rows_kernel(
    const float* __restrict__ q, const float* __restrict__ k,
    const float* __restrict__ v)
{
    const int sel = blockIdx.y;
    const float* src = (sel == 0) ? q : (sel == 1) ? k : v;
    __nv_bfloat16 *d0, *d1;
    if (sel == 0)      { d0 = g_qs[0]; d1 = g_qs[1]; }
    else if (sel == 1) { d0 = g_ks[0]; d1 = g_ks[1]; }
    else               { d0 = g_vs[0]; d1 = g_vs[1]; }

    for (int i = (blockIdx.x * blockDim.x + threadIdx.x) * 4; i < NEL;
         i += gridDim.x * blockDim.x * 4) {
        float4 x = *reinterpret_cast<const float4*>(src + i);
        uint32_t h0, l0, h1, l1;
        splitpair(x.x, x.y, h0, l0);
        splitpair(x.z, x.w, h1, l1);
        *reinterpret_cast<uint2*>(d0 + i) = make_uint2(h0, h1);
        *reinterpret_cast<uint2*>(d1 + i) = make_uint2(l0, l1);
    }
}

__global__ void __launch_bounds__(256) conv_w_kernel(
    const float* __restrict__ wq, const float* __restrict__ wk,
    const float* __restrict__ wv, const float* __restrict__ wo)
{
    const int sel = blockIdx.z;
    const float* W = (sel == 0) ? wq : (sel == 1) ? wk : (sel == 2) ? wv : wo;
    __nv_bfloat16 *d0, *d1;
    if (sel == 0)      { d0 = g_wqT[0]; d1 = g_wqT[1]; }
    else if (sel == 1) { d0 = g_wkT[0]; d1 = g_wkT[1]; }
    else if (sel == 2) { d0 = g_wvT[0]; d1 = g_wvT[1]; }
    else               { d0 = g_woT[0]; d1 = g_woT[1]; }

    __shared__ float tile[32][33];
    const int tx = threadIdx.x & 31;
    const int ty = threadIdx.x >> 5;
    const int ct = blockIdx.x;
    const int rt = blockIdx.y;

    #pragma unroll
    for (int i = 0; i < 4; i++) {
        const int d = rt * 32 + ty + i * 8;
        const int n = ct * 32 + tx;
        size_t idx;
        if (sel < 3) idx = ((size_t)(n >> 6) * DD + d) * RR + (n & 63);
        else         idx = (size_t)d * DD + n;
        tile[ty + i * 8][tx] = W[idx];
    }
    __syncthreads();
    #pragma unroll
    for (int i = 0; i < 4; i++) {
        const int nl = ty + i * 8;
        const int n  = ct * 32 + nl;
        const int d  = rt * 32 + tx;
        float x = tile[tx][nl];
        __nv_bfloat16 b0 = __float2bfloat16(x);
        size_t o = (size_t)n * DD + d;
        d0[o] = b0;
        d1[o] = __float2bfloat16(x - __bfloat162float(b0));
    }
}

// ---------------------------------------------------------------------------
// mma.sync split-bf16 GEMM — 48-stage schedule (the 626us config).
//   3 terms (hi*hi + hi*lo + lo*hi) folded into the stage stream.
//   kinds 0/1 -> bf16 planes; kind 2 -> fp16 planes; kind 3 -> fp32 out.
// ---------------------------------------------------------------------------
#define GEMM_SMEM 65536

__global__ void __launch_bounds__(256) gemm_kernel(float* __restrict__ outC,
                                                   int kind_base)
{
    const int kind = kind_base + blockIdx.z;
    const __nv_bfloat16 *Ax[2], *Bx[2];
    __nv_bfloat16 *P0 = nullptr, *P1 = nullptr;
    float scale = 1.0f;
    if (kind == 0)      { Ax[0] = g_qs[0]; Ax[1] = g_qs[1];
                          Bx[0] = g_wqT[0]; Bx[1] = g_wqT[1];
                          P0 = g_Qb[0]; P1 = g_Qb[1];
                          scale = 0.125f * 1.4426950408889634f; }
    else if (kind == 1) { Ax[0] = g_ks[0]; Ax[1] = g_ks[1];
                          Bx[0] = g_wkT[0]; Bx[1] = g_wkT[1];
                          P0 = g_Kb[0]; P1 = g_Kb[1]; }
    else if (kind == 2) { Ax[0] = g_vs[0]; Ax[1] = g_vs[1];
                          Bx[0] = g_wvT[0]; Bx[1] = g_wvT[1]; }
    else                { Ax[0] = g_os[0]; Ax[1] = g_os[1];
                          Bx[0] = g_woT[0]; Bx[1] = g_woT[1]; }
    const int ti[3] = {0, 0, 1};
    const int tj[3] = {0, 1, 0};
    const int NST = 48;

    extern __shared__ char smem[];
    const uint32_t sb = smem_u32(smem);
    const int t      = threadIdx.x;
    const int lane   = t & 31;
    const int wid    = t >> 5;
    const int warp_m = wid >> 2;
    const int warp_n = wid & 3;
    const int m0 = blockIdx.y * 128;
    const int n0 = blockIdx.x * 128;

    float acc[4][4][4];
    #pragma unroll
    for (int a = 0; a < 4; a++)
        #pragma unroll
        for (int b = 0; b < 4; b++)
            #pragma unroll
            for (int c = 0; c < 4; c++) acc[a][b][c] = 0.f;

    const int a_row  = warp_m * 64 + (lane & 15);
    const int a_koff = (lane >> 4) * 16;
    const int b_row  = warp_n * 32 + (lane & 7) + ((lane >> 4) & 1) * 8;
    const int b_koff = ((lane >> 3) & 1) * 16;

    {
        const __nv_bfloat16* Ag = Ax[0];
        const __nv_bfloat16* Bg = Bx[0];
        const uint32_t abase = sb, bbase = sb + 16384;
        #pragma unroll
        for (int it = 0; it < 4; it++) {
            const int cid = it * 256 + t;
            const int row = cid >> 3, c16 = cid & 7;
            cp16(abase + swz(row * 128 + c16 * 16),
                 Ag + (size_t)(m0 + row) * DD + c16 * 8);
            cp16(bbase + swz(row * 128 + c16 * 16),
                 Bg + (size_t)(n0 + row) * DD + c16 * 8);
        }
        CP_COMMIT();
    }

    for (int s = 0; s < NST; s++) {
        CP_WAIT0();
        __syncthreads();
        if (s + 1 < NST) {
            const int sn = s + 1;
            const int tt = sn >> 4;
            const int k0 = (sn & 15) * 64;
            const __nv_bfloat16* Ag = Ax[ti[tt]];
            const __nv_bfloat16* Bg = Bx[tj[tt]];
            const uint32_t abase = sb + (sn & 1) * 32768;
            const uint32_t bbase = abase + 16384;
            #pragma unroll
            for (int it = 0; it < 4; it++) {
                const int cid = it * 256 + t;
                const int row = cid >> 3, c16 = cid & 7;
                cp16(abase + swz(row * 128 + c16 * 16),
                     Ag + (size_t)(m0 + row) * DD + k0 + c16 * 8);
                cp16(bbase + swz(row * 128 + c16 * 16),
                     Bg + (size_t)(n0 + row) * DD + k0 + c16 * 8);
            }
            CP_COMMIT();
        }
        const uint32_t abase = sb + (s & 1) * 32768;
        const uint32_t bbase = abase + 16384;
        #pragma unroll
        for (int k16 = 0; k16 < 64; k16 += 16) {
            uint32_t ar[4][4], br[4][2];
            #pragma unroll
            for (int mi = 0; mi < 4; mi++) {
                const int row = a_row + mi * 16;
                ldm_x4(ar[mi], abase + swz(row * 128 + k16 * 2 + a_koff));
            }
            #pragma unroll
            for (int nb = 0; nb < 2; nb++) {
                const int n = b_row + nb * 16;
                uint32_t r[4];
                ldm_x4(r, bbase + swz(n * 128 + k16 * 2 + b_koff));
                br[nb * 2][0] = r[0]; br[nb * 2][1] = r[1];
                br[nb * 2 + 1][0] = r[2]; br[nb * 2 + 1][1] = r[3];
            }
            #pragma unroll
            for (int mi = 0; mi < 4; mi++)
                #pragma unroll
                for (int ni = 0; ni < 4; ni++)
                    mma_bf16(acc[mi][ni], ar[mi], br[ni]);
        }
    }

    // epilogue
    #pragma unroll
    for (int mi = 0; mi < 4; mi++) {
        #pragma unroll
        for (int ni = 0; ni < 4; ni++) {
            const int r0 = m0 + warp_m * 64 + mi * 16 + (lane >> 2);
            const int c  = n0 + warp_n * 32 + ni * 8 + (lane & 3) * 2;
            #pragma unroll
            for (int half = 0; half < 2; half++) {
                const int m = r0 + half * 8;
                float v0 = acc[mi][ni][half * 2] * scale;
                float v1 = acc[mi][ni][half * 2 + 1] * scale;
                if (kind < 2) {
                    const int h = c >> 6, r = c & 63;
                    const int b = m >> 11, sl = m & 2047;
                    size_t idx = (((size_t)b * HH + h) * SS + sl) * RR + r;
                    uint32_t hh, ll;
                    splitpair(v0, v1, hh, ll);
                    *reinterpret_cast<uint32_t*>(&P0[idx]) = hh;
                    *reinterpret_cast<uint32_t*>(&P1[idx]) = ll;
                } else if (kind == 2) {
                    const int h = c >> 6, r = c & 63;
                    const int b = m >> 11, sl = m & 2047;
                    size_t idx = (((size_t)b * HH + h) * SS + sl) * RR + r;
                    uint32_t hh, ll;
                    splitpair_h(v0, v1, hh, ll);
                    *reinterpret_cast<uint32_t*>(&g_Vh[0][idx]) = hh;
                    *reinterpret_cast<uint32_t*>(&g_Vh[1][idx]) = ll;
                } else {
                    *reinterpret_cast<float2*>(&outC[(size_t)m * DD + c]) =
                        make_float2(v0, v1);
                }
            }
        }
    }
}

// ---------------------------------------------------------------------------
// Tensor-core flash attention (exp2 domain, single barrier per stage).
//   GEMM1: bf16, 3 split terms.  GEMM2: fp16, P single + V hi/lo (4 mmas
//   per (kb,g) instead of 6; P rounding 2^-11 -> ~5e-4 output rel-err).
// ---------------------------------------------------------------------------
#define ATT_SMEM 98304

__global__ void __launch_bounds__(256, 2) attn_kernel()
{
    const int z  = blockIdx.y;
    const int s0 = blockIdx.x * 128;
    extern __shared__ char sm[];
    const uint32_t sb = smem_u32(sm);
    const int t = threadIdx.x, lane = t & 31, wid = t >> 5;
    const size_t zoff = (size_t)z * SS * RR;

    #define QOFF(p)      (sb + (p) * 16384u)
    #define KOFF(bf, p)  (sb + 32768u + (bf) * 32768u + (p) * 8192u)
    #define VOFF(bf, p)  (sb + 32768u + (bf) * 32768u + 16384u + (p) * 8192u)

    #pragma unroll
    for (int p = 0; p < 2; p++) {
        const __nv_bfloat16* src = g_Qb[p] + zoff + (size_t)s0 * RR;
        #pragma unroll
        for (int it = 0; it < 4; it++) {
            const int cid = it * 256 + t;
            const int row = cid >> 3, c16 = cid & 7;
            cp16(QOFF(p) + swz(row * 128 + c16 * 16), src + row * 64 + c16 * 8);
        }
    }
    #pragma unroll
    for (int p = 0; p < 2; p++) {
        #pragma unroll
        for (int it = 0; it < 2; it++) {
            const int cid = it * 256 + t;
            const int row = cid >> 3, c16 = cid & 7;
            cp16(KOFF(0, p) + swz(row * 128 + c16 * 16),
                 g_Kb[p] + zoff + (size_t)row * RR + c16 * 8);
            cp16(VOFF(0, p) + swz(row * 128 + c16 * 16),
                 g_Vh[p] + zoff + (size_t)row * RR + c16 * 8);
        }
    }
    CP_COMMIT();

    float m0r = -3.0e38f, m1r = -3.0e38f, l0r = 0.f, l1r = 0.f;
    float oa[8][4];
    #pragma unroll
    for (int b = 0; b < 8; b++)
        #pragma unroll
        for (int c = 0; c < 4; c++) oa[b][c] = 0.f;

    for (int s = 0; s < 32; s++) {
        const int buf = s & 1;
        CP_WAIT0();
        __syncthreads();
        if (s + 1 < 32) {
            const int nb = (s + 1) & 1;
            const int kv = (s + 1) * 64;
            #pragma unroll
            for (int p = 0; p < 2; p++) {
                #pragma unroll
                for (int it = 0; it < 2; it++) {
                    const int cid = it * 256 + t;
                    const int row = cid >> 3, c16 = cid & 7;
                    cp16(KOFF(nb, p) + swz(row * 128 + c16 * 16),
                         g_Kb[p] + zoff + (size_t)(kv + row) * RR + c16 * 8);
                    cp16(VOFF(nb, p) + swz(row * 128 + c16 * 16),
                         g_Vh[p] + zoff + (size_t)(kv + row) * RR + c16 * 8);
                }
            }
            CP_COMMIT();
        }

        // ---- GEMM1: S = Q K^T (bf16, 3 split terms) ----
        float sa[8][4];
        #pragma unroll
        for (int b = 0; b < 8; b++)
            #pragma unroll
            for (int c = 0; c < 4; c++) sa[b][c] = 0.f;

        #pragma unroll
        for (int kb = 0; kb < 4; kb++) {
            uint32_t aq[2][4];
            const int arow = wid * 16 + (lane & 15);
            const int akoff = kb * 32 + (lane >> 4) * 16;
            #pragma unroll
            for (int p = 0; p < 2; p++)
                ldm_x4(aq[p], QOFF(p) + swz(arow * 128 + akoff));
            #pragma unroll
            for (int g = 0; g < 4; g++) {
                uint32_t bk[2][4];
                const int brow = g * 16 + (lane & 7) + ((lane >> 4) & 1) * 8;
                const int bkoff = kb * 32 + ((lane >> 3) & 1) * 16;
                #pragma unroll
                for (int p = 0; p < 2; p++)
                    ldm_x4(bk[p], KOFF(buf, p) + swz(brow * 128 + bkoff));
                mma_bf16(sa[2 * g],     aq[0], &bk[0][0]);   // hi*hi
                mma_bf16(sa[2 * g + 1], aq[0], &bk[0][2]);
                mma_bf16(sa[2 * g],     aq[0], &bk[1][0]);   // hi*lo
                mma_bf16(sa[2 * g + 1], aq[0], &bk[1][2]);
                mma_bf16(sa[2 * g],     aq[1], &bk[0][0]);   // lo*hi
                mma_bf16(sa[2 * g + 1], aq[1], &bk[0][2]);
            }
        }

        // ---- online softmax (exp2 domain, MUFU ex2) ----
        float mt0 = -3.0e38f, mt1 = -3.0e38f;
        #pragma unroll
        for (int b = 0; b < 8; b++) {
            mt0 = fmaxf(mt0, fmaxf(sa[b][0], sa[b][1]));
            mt1 = fmaxf(mt1, fmaxf(sa[b][2], sa[b][3]));
        }
        mt0 = fmaxf(mt0, __shfl_xor_sync(0xffffffffu, mt0, 1));
        mt0 = fmaxf(mt0, __shfl_xor_sync(0xffffffffu, mt0, 2));
        mt1 = fmaxf(mt1, __shfl_xor_sync(0xffffffffu, mt1, 1));
        mt1 = fmaxf(mt1, __shfl_xor_sync(0xffffffffu, mt1, 2));
        const float mn0 = fmaxf(m0r, mt0), mn1 = fmaxf(m1r, mt1);
        const float al0 = ex2f(m0r - mn0), al1 = ex2f(m1r - mn1);
        m0r = mn0; m1r = mn1;
        float rs0 = 0.f, rs1 = 0.f;
        #pragma unroll
        for (int b = 0; b < 8; b++) {
            sa[b][0] = ex2f(sa[b][0] - mn0);
            sa[b][1] = ex2f(sa[b][1] - mn0);
            sa[b][2] = ex2f(sa[b][2] - mn1);
            sa[b][3] = ex2f(sa[b][3] - mn1);
            rs0 += sa[b][0] + sa[b][1];
            rs1 += sa[b][2] + sa[b][3];
        }
        rs0 += __shfl_xor_sync(0xffffffffu, rs0, 1);
        rs0 += __shfl_xor_sync(0xffffffffu, rs0, 2);
        rs1 += __shfl_xor_sync(0xffffffffu, rs1, 1);
        rs1 += __shfl_xor_sync(0xffffffffu, rs1, 2);
        l0r = l0r * al0 + rs0;
        l1r = l1r * al1 + rs1;
        #pragma unroll
        for (int b = 0; b < 8; b++) {
            oa[b][0] *= al0; oa[b][1] *= al0;
            oa[b][2] *= al1; oa[b][3] *= al1;
        }

        // ---- GEMM2: O += P V (fp16: P single, V hi/lo) ----
        #pragma unroll
        for (int kb = 0; kb < 4; kb++) {
            uint32_t pp[4];
            pp[0] = packh2(sa[2 * kb][0],     sa[2 * kb][1]);
            pp[1] = packh2(sa[2 * kb][2],     sa[2 * kb][3]);
            pp[2] = packh2(sa[2 * kb + 1][0], sa[2 * kb + 1][1]);
            pp[3] = packh2(sa[2 * kb + 1][2], sa[2 * kb + 1][3]);
            #pragma unroll
            for (int g = 0; g < 4; g++) {
                uint32_t bv[2][4];
                const int trow = kb * 16 + (lane & 7) + ((lane >> 3) & 1) * 8;
                const int rbyte = g * 32 + ((lane >> 4) & 1) * 16;
                #pragma unroll
                for (int p = 0; p < 2; p++)
                    ldm_x4_t(bv[p], VOFF(buf, p) + swz(trow * 128 + rbyte));
                mma_f16(oa[2 * g],     pp, &bv[0][0]);   // P * V_hi
                mma_f16(oa[2 * g],     pp, &bv[1][0]);   // P * V_lo
                mma_f16(oa[2 * g + 1], pp, &bv[0][2]);
                mma_f16(oa[2 * g + 1], pp, &bv[1][2]);
            }
        }
    }

    // ---- epilogue: O/l -> g_os bf16 planes ----
    const float i0 = rcpf(l0r), i1 = rcpf(l1r);
    #pragma unroll
    for (int b = 0; b < 8; b++) {
        const int r   = b * 8 + (lane & 3) * 2;
        const int r0w = s0 + wid * 16 + (lane >> 2);
        uint32_t hh, ll;
        size_t idx = zoff + (size_t)r0w * RR + r;
        splitpair(oa[b][0] * i0, oa[b][1] * i0, hh, ll);
        *reinterpret_cast<uint32_t*>(&g_os[0][idx]) = hh;
        *reinterpret_cast<uint32_t*>(&g_os[1][idx]) = ll;
        idx = zoff + (size_t)(r0w + 8) * RR + r;
        splitpair(oa[b][2] * i1, oa[b][3] * i1, hh, ll);
        *reinterpret_cast<uint32_t*>(&g_os[0][idx]) = hh;
        *reinterpret_cast<uint32_t*>(&g_os[1][idx]) = ll;
    }
    #undef QOFF
    #undef KOFF
    #undef VOFF
}

// ---------------------------------------------------------------------------
// Launch
// ---------------------------------------------------------------------------
extern "C" void kernel_launch(void* const* d_in, const int* in_sizes, int n_in,
                              void* d_out, int out_size)
{
    const float* q  = (const float*)d_in[0];
    const float* k  = (const float*)d_in[1];
    const float* v  = (const float*)d_in[2];
    const float* wq = (const float*)d_in[3];
    const float* wk = (const float*)d_in[4];
    const float* wv = (const float*)d_in[5];
    const float* wo = (const float*)d_in[6];
    float* out = (float*)d_out;

    (void)in_sizes; (void)n_in; (void)out_size;

    cudaFuncSetAttribute(gemm_kernel,
                         cudaFuncAttributeMaxDynamicSharedMemorySize, GEMM_SMEM);
    cudaFuncSetAttribute(attn_kernel,
                         cudaFuncAttributeMaxDynamicSharedMemorySize, ATT_SMEM);

    // 1) split inputs + weights to bf16 hi/lo
    conv_rows_kernel<<<dim3(1024, 3), 256>>>(q, k, v);
    conv_w_kernel<<<dim3(32, 32, 4), 256>>>(wq, wk, wv, wo);

    // 2) Q/K/V projections (Q pre-scaled by log2e/8; V -> fp16 planes)
    gemm_kernel<<<dim3(8, 32, 3), 256, GEMM_SMEM>>>(nullptr, 0);

    // 3) tensor-core flash attention -> g_os planes
    attn_kernel<<<dim3(16, 32), 256, ATT_SMEM>>>();

    // 4) output projection -> fp32 out
    gemm_kernel<<<dim3(8, 32, 1), 256, GEMM_SMEM>>>(out, 3);
}

// round 13
// speedup vs baseline: 1.3092x; 1.1124x over previous
#include <cuda_runtime.h>
#include <cuda_bf16.h>
#include <cuda_fp16.h>
#include <cstdint>

// ---------------------------------------------------------------------------
// Problem constants
// ---------------------------------------------------------------------------
#define BB 2
#define SS 2048
#define DD 1024
#define HH 16
#define RR 64
#define BH (BB * HH)   // 32
#define NEL (BB * SS * DD)

// ---------------------------------------------------------------------------
// mma.sync helpers (baseline PTX, plain sm_100 target)
// ---------------------------------------------------------------------------
__device__ __forceinline__ uint32_t smem_u32(const void* p) {
    uint32_t a;
    asm("{ .reg .u64 t; cvta.to.shared.u64 t, %1; cvt.u32.u64 %0, t; }"
        : "=r"(a) : "l"(p));
    return a;
}
__device__ __forceinline__ void ldm_x4(uint32_t* r, uint32_t addr) {
    asm volatile("ldmatrix.sync.aligned.m8n8.x4.shared.b16 {%0,%1,%2,%3}, [%4];"
                 : "=r"(r[0]), "=r"(r[1]), "=r"(r[2]), "=r"(r[3]) : "r"(addr));
}
__device__ __forceinline__ void ldm_x4_t(uint32_t* r, uint32_t addr) {
    asm volatile("ldmatrix.sync.aligned.m8n8.x4.trans.shared.b16 {%0,%1,%2,%3}, [%4];"
                 : "=r"(r[0]), "=r"(r[1]), "=r"(r[2]), "=r"(r[3]) : "r"(addr));
}
__device__ __forceinline__ void mma_bf16(float* c, const uint32_t* a,
                                         const uint32_t* b) {
    asm volatile(
        "mma.sync.aligned.m16n8k16.row.col.f32.bf16.bf16.f32 "
        "{%0,%1,%2,%3}, {%4,%5,%6,%7}, {%8,%9}, {%0,%1,%2,%3};"
        : "+f"(c[0]), "+f"(c[1]), "+f"(c[2]), "+f"(c[3])
        : "r"(a[0]), "r"(a[1]), "r"(a[2]), "r"(a[3]), "r"(b[0]), "r"(b[1]));
}
__device__ __forceinline__ void mma_f16(float* c, const uint32_t* a,
                                        const uint32_t* b) {
    asm volatile(
        "mma.sync.aligned.m16n8k16.row.col.f32.f16.f16.f32 "
        "{%0,%1,%2,%3}, {%4,%5,%6,%7}, {%8,%9}, {%0,%1,%2,%3};"
        : "+f"(c[0]), "+f"(c[1]), "+f"(c[2]), "+f"(c[3])
        : "r"(a[0]), "r"(a[1]), "r"(a[2]), "r"(a[3]), "r"(b[0]), "r"(b[1]));
}
__device__ __forceinline__ void cp16(uint32_t dst, const void* src) {
    asm volatile("cp.async.cg.shared.global [%0], [%1], 16;"
                 :: "r"(dst), "l"(__cvta_generic_to_global(src)));
}
#define CP_COMMIT() asm volatile("cp.async.commit_group;" ::: "memory")
#define CP_WAIT0()  asm volatile("cp.async.wait_group 0;" ::: "memory")

__device__ __forceinline__ uint32_t swz(uint32_t o) { return o ^ ((o >> 3) & 0x70); }

__device__ __forceinline__ float ex2f(float x) {
    float y;
    asm("ex2.approx.ftz.f32 %0, %1;" : "=f"(y) : "f"(x));
    return y;
}
__device__ __forceinline__ float rcpf(float x) {
    float y;
    asm("rcp.approx.ftz.f32 %0, %1;" : "=f"(y) : "f"(x));
    return y;
}

// Split a float pair into bf16 hi/lo packed u32s (rn rounding).
__device__ __forceinline__ void splitpair(float x, float y,
                                          uint32_t& h, uint32_t& l) {
    asm("cvt.rn.bf16x2.f32 %0, %1, %2;" : "=r"(h) : "f"(y), "f"(x));
    float hx = __uint_as_float(h << 16);
    float hy = __uint_as_float(h & 0xFFFF0000u);
    asm("cvt.rn.bf16x2.f32 %0, %1, %2;" : "=r"(l) : "f"(y - hy), "f"(x - hx));
}
// fp16 variant
__device__ __forceinline__ void splitpair_h(float x, float y,
                                            uint32_t& h, uint32_t& l) {
    __half2 H = __floats2half2_rn(x, y);
    h = *reinterpret_cast<uint32_t*>(&H);
    float2 hf = __half22float2(H);
    __half2 L = __floats2half2_rn(x - hf.x, y - hf.y);
    l = *reinterpret_cast<uint32_t*>(&L);
}
__device__ __forceinline__ uint32_t packh2(float x, float y) {
    __half2 H = __floats2half2_rn(x, y);
    return *reinterpret_cast<uint32_t*>(&H);
}

// ---------------------------------------------------------------------------
// Scratch
// ---------------------------------------------------------------------------
__device__ __nv_bfloat16 g_qs[2][NEL];
__device__ __nv_bfloat16 g_ks[2][NEL];
__device__ __nv_bfloat16 g_vs[2][NEL];
__device__ __nv_bfloat16 g_wqT[2][DD * DD];
__device__ __nv_bfloat16 g_wkT[2][DD * DD];
__device__ __nv_bfloat16 g_wvT[2][DD * DD];
__device__ __half        g_woH[2][DD * DD];     // wo fp16 hi/lo, transposed
// projection outputs, [b,h,s,r] layout:
//   Q/K bf16 hi/lo planes (Q pre-scaled by 0.125*log2e, exp2 domain)
//   V  single fp16 plane (storage noise ~2^-11, sqrt-N cancels in P*V)
__device__ __nv_bfloat16 g_Qb[2][BH * SS * RR];
__device__ __nv_bfloat16 g_Kb[2][BH * SS * RR];
__device__ __half        g_Vh[BH * SS * RR];
// attention output, single fp16 plane, [z][s][r] == flat [4096][1024]
__device__ __half        g_oh[NEL];

// ---------------------------------------------------------------------------
// fp32 -> 2-way bf16 split converter (q/k/v fused via blockIdx.y)
// ---------------------------------------------------------------------------
__global__ void __launch_bounds__(256) conv_rows_kernel(
    const float* __restrict__ q, const float* __restrict__ k,
    const float* __restrict__ v)
{
    const int sel = blockIdx.y;
    const float* src = (sel == 0) ? q : (sel == 1) ? k : v;
    __nv_bfloat16 *d0, *d1;
    if (sel == 0)      { d0 = g_qs[0]; d1 = g_qs[1]; }
    else if (sel == 1) { d0 = g_ks[0]; d1 = g_ks[1]; }
    else               { d0 = g_vs[0]; d1 = g_vs[1]; }

    for (int i = (blockIdx.x * blockDim.x + threadIdx.x) * 4; i < NEL;
         i += gridDim.x * blockDim.x * 4) {
        float4 x = *reinterpret_cast<const float4*>(src + i);
        uint32_t h0, l0, h1, l1;
        splitpair(x.x, x.y, h0, l0);
        splitpair(x.z, x.w, h1, l1);
        *reinterpret_cast<uint2*>(d0 + i) = make_uint2(h0, h1);
        *reinterpret_cast<uint2*>(d1 + i) = make_uint2(l0, l1);
    }
}

// Weight transpose + split. sel 0..2 -> bf16 planes; sel 3 (wo) -> fp16 planes.
__global__ void __launch_bounds__(256) conv_w_kernel(
    const float* __restrict__ wq, const float* __restrict__ wk,
    const float* __restrict__ wv, const float* __restrict__ wo)
{
    const int sel = blockIdx.z;
    const float* W = (sel == 0) ? wq : (sel == 1) ? wk : (sel == 2) ? wv : wo;
    __nv_bfloat16 *d0 = nullptr, *d1 = nullptr;
    if (sel == 0)      { d0 = g_wqT[0]; d1 = g_wqT[1]; }
    else if (sel == 1) { d0 = g_wkT[0]; d1 = g_wkT[1]; }
    else if (sel == 2) { d0 = g_wvT[0]; d1 = g_wvT[1]; }

    __shared__ float tile[32][33];
    const int tx = threadIdx.x & 31;
    const int ty = threadIdx.x >> 5;
    const int ct = blockIdx.x;
    const int rt = blockIdx.y;

    #pragma unroll
    for (int i = 0; i < 4; i++) {
        const int d = rt * 32 + ty + i * 8;
        const int n = ct * 32 + tx;
        size_t idx;
        if (sel < 3) idx = ((size_t)(n >> 6) * DD + d) * RR + (n & 63);
        else         idx = (size_t)d * DD + n;
        tile[ty + i * 8][tx] = W[idx];
    }
    __syncthreads();
    #pragma unroll
    for (int i = 0; i < 4; i++) {
        const int nl = ty + i * 8;
        const int n  = ct * 32 + nl;
        const int d  = rt * 32 + tx;
        float x = tile[tx][nl];
        size_t o = (size_t)n * DD + d;
        if (sel < 3) {
            __nv_bfloat16 b0 = __float2bfloat16(x);
            d0[o] = b0;
            d1[o] = __float2bfloat16(x - __bfloat162float(b0));
        } else {
            __half h0 = __float2half_rn(x);
            g_woH[0][o] = h0;
            g_woH[1][o] = __float2half_rn(x - __half2float(h0));
        }
    }
}

// ---------------------------------------------------------------------------
// mma.sync split-bf16 GEMM for Q/K/V projections (48-stage, 3 terms).
//   kinds 0/1 -> bf16 hi/lo planes; kind 2 -> single fp16 plane (g_Vh).
// ---------------------------------------------------------------------------
#define GEMM_SMEM 65536

__global__ void __launch_bounds__(256) gemm_kernel()
{
    const int kind = blockIdx.z;
    const __nv_bfloat16 *Ax[2], *Bx[2];
    __nv_bfloat16 *P0 = nullptr, *P1 = nullptr;
    float scale = 1.0f;
    if (kind == 0)      { Ax[0] = g_qs[0]; Ax[1] = g_qs[1];
                          Bx[0] = g_wqT[0]; Bx[1] = g_wqT[1];
                          P0 = g_Qb[0]; P1 = g_Qb[1];
                          scale = 0.125f * 1.4426950408889634f; }
    else if (kind == 1) { Ax[0] = g_ks[0]; Ax[1] = g_ks[1];
                          Bx[0] = g_wkT[0]; Bx[1] = g_wkT[1];
                          P0 = g_Kb[0]; P1 = g_Kb[1]; }
    else                { Ax[0] = g_vs[0]; Ax[1] = g_vs[1];
                          Bx[0] = g_wvT[0]; Bx[1] = g_wvT[1]; }
    const int ti[3] = {0, 0, 1};
    const int tj[3] = {0, 1, 0};
    const int NST = 48;

    extern __shared__ char smem[];
    const uint32_t sb = smem_u32(smem);
    const int t      = threadIdx.x;
    const int lane   = t & 31;
    const int wid    = t >> 5;
    const int warp_m = wid >> 2;
    const int warp_n = wid & 3;
    const int m0 = blockIdx.y * 128;
    const int n0 = blockIdx.x * 128;

    float acc[4][4][4];
    #pragma unroll
    for (int a = 0; a < 4; a++)
        #pragma unroll
        for (int b = 0; b < 4; b++)
            #pragma unroll
            for (int c = 0; c < 4; c++) acc[a][b][c] = 0.f;

    const int a_row  = warp_m * 64 + (lane & 15);
    const int a_koff = (lane >> 4) * 16;
    const int b_row  = warp_n * 32 + (lane & 7) + ((lane >> 4) & 1) * 8;
    const int b_koff = ((lane >> 3) & 1) * 16;

    {
        const uint32_t abase = sb, bbase = sb + 16384;
        #pragma unroll
        for (int it = 0; it < 4; it++) {
            const int cid = it * 256 + t;
            const int row = cid >> 3, c16 = cid & 7;
            cp16(abase + swz(row * 128 + c16 * 16),
                 Ax[0] + (size_t)(m0 + row) * DD + c16 * 8);
            cp16(bbase + swz(row * 128 + c16 * 16),
                 Bx[0] + (size_t)(n0 + row) * DD + c16 * 8);
        }
        CP_COMMIT();
    }

    for (int s = 0; s < NST; s++) {
        CP_WAIT0();
        __syncthreads();
        if (s + 1 < NST) {
            const int sn = s + 1;
            const int tt = sn >> 4;
            const int k0 = (sn & 15) * 64;
            const __nv_bfloat16* Ag = Ax[ti[tt]];
            const __nv_bfloat16* Bg = Bx[tj[tt]];
            const uint32_t abase = sb + (sn & 1) * 32768;
            const uint32_t bbase = abase + 16384;
            #pragma unroll
            for (int it = 0; it < 4; it++) {
                const int cid = it * 256 + t;
                const int row = cid >> 3, c16 = cid & 7;
                cp16(abase + swz(row * 128 + c16 * 16),
                     Ag + (size_t)(m0 + row) * DD + k0 + c16 * 8);
                cp16(bbase + swz(row * 128 + c16 * 16),
                     Bg + (size_t)(n0 + row) * DD + k0 + c16 * 8);
            }
            CP_COMMIT();
        }
        const uint32_t abase = sb + (s & 1) * 32768;
        const uint32_t bbase = abase + 16384;
        #pragma unroll
        for (int k16 = 0; k16 < 64; k16 += 16) {
            uint32_t ar[4][4], br[4][2];
            #pragma unroll
            for (int mi = 0; mi < 4; mi++) {
                const int row = a_row + mi * 16;
                ldm_x4(ar[mi], abase + swz(row * 128 + k16 * 2 + a_koff));
            }
            #pragma unroll
            for (int nb = 0; nb < 2; nb++) {
                const int n = b_row + nb * 16;
                uint32_t r[4];
                ldm_x4(r, bbase + swz(n * 128 + k16 * 2 + b_koff));
                br[nb * 2][0] = r[0]; br[nb * 2][1] = r[1];
                br[nb * 2 + 1][0] = r[2]; br[nb * 2 + 1][1] = r[3];
            }
            #pragma unroll
            for (int mi = 0; mi < 4; mi++)
                #pragma unroll
                for (int ni = 0; ni < 4; ni++)
                    mma_bf16(acc[mi][ni], ar[mi], br[ni]);
        }
    }

    // epilogue
    #pragma unroll
    for (int mi = 0; mi < 4; mi++) {
        #pragma unroll
        for (int ni = 0; ni < 4; ni++) {
            const int r0 = m0 + warp_m * 64 + mi * 16 + (lane >> 2);
            const int c  = n0 + warp_n * 32 + ni * 8 + (lane & 3) * 2;
            #pragma unroll
            for (int half = 0; half < 2; half++) {
                const int m = r0 + half * 8;
                float v0 = acc[mi][ni][half * 2] * scale;
                float v1 = acc[mi][ni][half * 2 + 1] * scale;
                const int h = c >> 6, r = c & 63;
                const int b = m >> 11, sl = m & 2047;
                size_t idx = (((size_t)b * HH + h) * SS + sl) * RR + r;
                if (kind < 2) {
                    uint32_t hh, ll;
                    splitpair(v0, v1, hh, ll);
                    *reinterpret_cast<uint32_t*>(&P0[idx]) = hh;
                    *reinterpret_cast<uint32_t*>(&P1[idx]) = ll;
                } else {
                    *reinterpret_cast<uint32_t*>(&g_Vh[idx]) = packh2(v0, v1);
                }
            }
        }
    }
}

// ---------------------------------------------------------------------------
// Output projection: out = g_oh (fp16 [4096x1024]) @ woH (fp16 hi/lo planes).
//   2 terms (A*Bh + A*Bl), 32 stages, f16 mma.
// ---------------------------------------------------------------------------
__global__ void __launch_bounds__(256) out_kernel(float* __restrict__ outC)
{
    const int NST = 32;
    extern __shared__ char smem[];
    const uint32_t sb = smem_u32(smem);
    const int t      = threadIdx.x;
    const int lane   = t & 31;
    const int wid    = t >> 5;
    const int warp_m = wid >> 2;
    const int warp_n = wid & 3;
    const int m0 = blockIdx.y * 128;
    const int n0 = blockIdx.x * 128;

    float acc[4][4][4];
    #pragma unroll
    for (int a = 0; a < 4; a++)
        #pragma unroll
        for (int b = 0; b < 4; b++)
            #pragma unroll
            for (int c = 0; c < 4; c++) acc[a][b][c] = 0.f;

    const int a_row  = warp_m * 64 + (lane & 15);
    const int a_koff = (lane >> 4) * 16;
    const int b_row  = warp_n * 32 + (lane & 7) + ((lane >> 4) & 1) * 8;
    const int b_koff = ((lane >> 3) & 1) * 16;

    {
        const uint32_t abase = sb, bbase = sb + 16384;
        #pragma unroll
        for (int it = 0; it < 4; it++) {
            const int cid = it * 256 + t;
            const int row = cid >> 3, c16 = cid & 7;
            cp16(abase + swz(row * 128 + c16 * 16),
                 g_oh + (size_t)(m0 + row) * DD + c16 * 8);
            cp16(bbase + swz(row * 128 + c16 * 16),
                 g_woH[0] + (size_t)(n0 + row) * DD + c16 * 8);
        }
        CP_COMMIT();
    }

    for (int s = 0; s < NST; s++) {
        CP_WAIT0();
        __syncthreads();
        if (s + 1 < NST) {
            const int sn = s + 1;
            const int tt = sn >> 4;                 // B plane
            const int k0 = (sn & 15) * 64;
            const uint32_t abase = sb + (sn & 1) * 32768;
            const uint32_t bbase = abase + 16384;
            #pragma unroll
            for (int it = 0; it < 4; it++) {
                const int cid = it * 256 + t;
                const int row = cid >> 3, c16 = cid & 7;
                cp16(abase + swz(row * 128 + c16 * 16),
                     g_oh + (size_t)(m0 + row) * DD + k0 + c16 * 8);
                cp16(bbase + swz(row * 128 + c16 * 16),
                     g_woH[tt] + (size_t)(n0 + row) * DD + k0 + c16 * 8);
            }
            CP_COMMIT();
        }
        const uint32_t abase = sb + (s & 1) * 32768;
        const uint32_t bbase = abase + 16384;
        #pragma unroll
        for (int k16 = 0; k16 < 64; k16 += 16) {
            uint32_t ar[4][4], br[4][2];
            #pragma unroll
            for (int mi = 0; mi < 4; mi++) {
                const int row = a_row + mi * 16;
                ldm_x4(ar[mi], abase + swz(row * 128 + k16 * 2 + a_koff));
            }
            #pragma unroll
            for (int nb = 0; nb < 2; nb++) {
                const int n = b_row + nb * 16;
                uint32_t r[4];
                ldm_x4(r, bbase + swz(n * 128 + k16 * 2 + b_koff));
                br[nb * 2][0] = r[0]; br[nb * 2][1] = r[1];
                br[nb * 2 + 1][0] = r[2]; br[nb * 2 + 1][1] = r[3];
            }
            #pragma unroll
            for (int mi = 0; mi < 4; mi++)
                #pragma unroll
                for (int ni = 0; ni < 4; ni++)
                    mma_f16(acc[mi][ni], ar[mi], br[ni]);
        }
    }

    #pragma unroll
    for (int mi = 0; mi < 4; mi++) {
        #pragma unroll
        for (int ni = 0; ni < 4; ni++) {
            const int r0 = m0 + warp_m * 64 + mi * 16 + (lane >> 2);
            const int c  = n0 + warp_n * 32 + ni * 8 + (lane & 3) * 2;
            #pragma unroll
            for (int half = 0; half < 2; half++) {
                const int m = r0 + half * 8;
                *reinterpret_cast<float2*>(&outC[(size_t)m * DD + c]) =
                    make_float2(acc[mi][ni][half * 2],
                                acc[mi][ni][half * 2 + 1]);
            }
        }
    }
}

// ---------------------------------------------------------------------------
// Tensor-core flash attention.
//   GEMM1: bf16, 3 split terms (96 mmas).  GEMM2: fp16 P * single fp16 V
//   (32 mmas).  exp2-domain softmax, single barrier per stage.
// ---------------------------------------------------------------------------
#define ATT_SMEM 81920

__global__ void __launch_bounds__(256, 2) attn_kernel()
{
    const int z  = blockIdx.y;
    const int s0 = blockIdx.x * 128;
    extern __shared__ char sm[];
    const uint32_t sb = smem_u32(sm);
    const int t = threadIdx.x, lane = t & 31, wid = t >> 5;
    const size_t zoff = (size_t)z * SS * RR;

    #define QOFF(p)      (sb + (p) * 16384u)
    #define KOFF(bf, p)  (sb + 32768u + (bf) * 24576u + (p) * 8192u)
    #define VOFF(bf)     (sb + 32768u + (bf) * 24576u + 16384u)

    #pragma unroll
    for (int p = 0; p < 2; p++) {
        const __nv_bfloat16* src = g_Qb[p] + zoff + (size_t)s0 * RR;
        #pragma unroll
        for (int it = 0; it < 4; it++) {
            const int cid = it * 256 + t;
            const int row = cid >> 3, c16 = cid & 7;
            cp16(QOFF(p) + swz(row * 128 + c16 * 16), src + row * 64 + c16 * 8);
        }
    }
    #pragma unroll
    for (int it = 0; it < 2; it++) {
        const int cid = it * 256 + t;
        const int row = cid >> 3, c16 = cid & 7;
        cp16(KOFF(0, 0) + swz(row * 128 + c16 * 16),
             g_Kb[0] + zoff + (size_t)row * RR + c16 * 8);
        cp16(KOFF(0, 1) + swz(row * 128 + c16 * 16),
             g_Kb[1] + zoff + (size_t)row * RR + c16 * 8);
        cp16(VOFF(0) + swz(row * 128 + c16 * 16),
             g_Vh + zoff + (size_t)row * RR + c16 * 8);
    }
    CP_COMMIT();

    float m0r = -3.0e38f, m1r = -3.0e38f, l0r = 0.f, l1r = 0.f;
    float oa[8][4];
    #pragma unroll
    for (int b = 0; b < 8; b++)
        #pragma unroll
        for (int c = 0; c < 4; c++) oa[b][c] = 0.f;

    for (int s = 0; s < 32; s++) {
        const int buf = s & 1;
        CP_WAIT0();
        __syncthreads();
        if (s + 1 < 32) {
            const int nb = (s + 1) & 1;
            const int kv = (s + 1) * 64;
            #pragma unroll
            for (int it = 0; it < 2; it++) {
                const int cid = it * 256 + t;
                const int row = cid >> 3, c16 = cid & 7;
                cp16(KOFF(nb, 0) + swz(row * 128 + c16 * 16),
                     g_Kb[0] + zoff + (size_t)(kv + row) * RR + c16 * 8);
                cp16(KOFF(nb, 1) + swz(row * 128 + c16 * 16),
                     g_Kb[1] + zoff + (size_t)(kv + row) * RR + c16 * 8);
                cp16(VOFF(nb) + swz(row * 128 + c16 * 16),
                     g_Vh + zoff + (size_t)(kv + row) * RR + c16 * 8);
            }
            CP_COMMIT();
        }

        // ---- GEMM1: S = Q K^T (bf16, 3 split terms) ----
        float sa[8][4];
        #pragma unroll
        for (int b = 0; b < 8; b++)
            #pragma unroll
            for (int c = 0; c < 4; c++) sa[b][c] = 0.f;

        #pragma unroll
        for (int kb = 0; kb < 4; kb++) {
            uint32_t aq[2][4];
            const int arow = wid * 16 + (lane & 15);
            const int akoff = kb * 32 + (lane >> 4) * 16;
            #pragma unroll
            for (int p = 0; p < 2; p++)
                ldm_x4(aq[p], QOFF(p) + swz(arow * 128 + akoff));
            #pragma unroll
            for (int g = 0; g < 4; g++) {
                uint32_t bk[2][4];
                const int brow = g * 16 + (lane & 7) + ((lane >> 4) & 1) * 8;
                const int bkoff = kb * 32 + ((lane >> 3) & 1) * 16;
                #pragma unroll
                for (int p = 0; p < 2; p++)
                    ldm_x4(bk[p], KOFF(buf, p) + swz(brow * 128 + bkoff));
                mma_bf16(sa[2 * g],     aq[0], &bk[0][0]);   // hi*hi
                mma_bf16(sa[2 * g + 1], aq[0], &bk[0][2]);
                mma_bf16(sa[2 * g],     aq[0], &bk[1][0]);   // hi*lo
                mma_bf16(sa[2 * g + 1], aq[0], &bk[1][2]);
                mma_bf16(sa[2 * g],     aq[1], &bk[0][0]);   // lo*hi
                mma_bf16(sa[2 * g + 1], aq[1], &bk[0][2]);
            }
        }

        // ---- online softmax (exp2 domain, MUFU ex2) ----
        float mt0 = -3.0e38f, mt1 = -3.0e38f;
        #pragma unroll
        for (int b = 0; b < 8; b++) {
            mt0 = fmaxf(mt0, fmaxf(sa[b][0], sa[b][1]));
            mt1 = fmaxf(mt1, fmaxf(sa[b][2], sa[b][3]));
        }
        mt0 = fmaxf(mt0, __shfl_xor_sync(0xffffffffu, mt0, 1));
        mt0 = fmaxf(mt0, __shfl_xor_sync(0xffffffffu, mt0, 2));
        mt1 = fmaxf(mt1, __shfl_xor_sync(0xffffffffu, mt1, 1));
        mt1 = fmaxf(mt1, __shfl_xor_sync(0xffffffffu, mt1, 2));
        const float mn0 = fmaxf(m0r, mt0), mn1 = fmaxf(m1r, mt1);
        const float al0 = ex2f(m0r - mn0), al1 = ex2f(m1r - mn1);
        m0r = mn0; m1r = mn1;
        float rs0 = 0.f, rs1 = 0.f;
        #pragma unroll
        for (int b = 0; b < 8; b++) {
            sa[b][0] = ex2f(sa[b][0] - mn0);
            sa[b][1] = ex2f(sa[b][1] - mn0);
            sa[b][2] = ex2f(sa[b][2] - mn1);
            sa[b][3] = ex2f(sa[b][3] - mn1);
            rs0 += sa[b][0] + sa[b][1];
            rs1 += sa[b][2] + sa[b][3];
        }
        rs0 += __shfl_xor_sync(0xffffffffu, rs0, 1);
        rs0 += __shfl_xor_sync(0xffffffffu, rs0, 2);
        rs1 += __shfl_xor_sync(0xffffffffu, rs1, 1);
        rs1 += __shfl_xor_sync(0xffffffffu, rs1, 2);
        l0r = l0r * al0 + rs0;
        l1r = l1r * al1 + rs1;
        #pragma unroll
        for (int b = 0; b < 8; b++) {
            oa[b][0] *= al0; oa[b][1] *= al0;
            oa[b][2] *= al1; oa[b][3] *= al1;
        }

        // ---- GEMM2: O += P V (fp16 P, single fp16 V) ----
        #pragma unroll
        for (int kb = 0; kb < 4; kb++) {
            uint32_t pp[4];
            pp[0] = packh2(sa[2 * kb][0],     sa[2 * kb][1]);
            pp[1] = packh2(sa[2 * kb][2],     sa[2 * kb][3]);
            pp[2] = packh2(sa[2 * kb + 1][0], sa[2 * kb + 1][1]);
            pp[3] = packh2(sa[2 * kb + 1][2], sa[2 * kb + 1][3]);
            #pragma unroll
            for (int g = 0; g < 4; g++) {
                uint32_t bv[4];
                const int trow = kb * 16 + (lane & 7) + ((lane >> 3) & 1) * 8;
                const int rbyte = g * 32 + ((lane >> 4) & 1) * 16;
                ldm_x4_t(bv, VOFF(buf) + swz(trow * 128 + rbyte));
                mma_f16(oa[2 * g],     pp, &bv[0]);
                mma_f16(oa[2 * g + 1], pp, &bv[2]);
            }
        }
    }

    // ---- epilogue: O/l -> g_oh single fp16 plane ----
    const float i0 = rcpf(l0r), i1 = rcpf(l1r);
    #pragma unroll
    for (int b = 0; b < 8; b++) {
        const int r   = b * 8 + (lane & 3) * 2;
        const int r0w = s0 + wid * 16 + (lane >> 2);
        size_t idx = zoff + (size_t)r0w * RR + r;
        *reinterpret_cast<uint32_t*>(&g_oh[idx]) =
            packh2(oa[b][0] * i0, oa[b][1] * i0);
        idx = zoff + (size_t)(r0w + 8) * RR + r;
        *reinterpret_cast<uint32_t*>(&g_oh[idx]) =
            packh2(oa[b][2] * i1, oa[b][3] * i1);
    }
    #undef QOFF
    #undef KOFF
    #undef VOFF
}

// ---------------------------------------------------------------------------
// Launch
// ---------------------------------------------------------------------------
extern "C" void kernel_launch(void* const* d_in, const int* in_sizes, int n_in,
                              void* d_out, int out_size)
{
    const float* q  = (const float*)d_in[0];
    const float* k  = (const float*)d_in[1];
    const float* v  = (const float*)d_in[2];
    const float* wq = (const float*)d_in[3];
    const float* wk = (const float*)d_in[4];
    const float* wv = (const float*)d_in[5];
    const float* wo = (const float*)d_in[6];
    float* out = (float*)d_out;

    (void)in_sizes; (void)n_in; (void)out_size;

    cudaFuncSetAttribute(gemm_kernel,
                         cudaFuncAttributeMaxDynamicSharedMemorySize, GEMM_SMEM);
    cudaFuncSetAttribute(out_kernel,
                         cudaFuncAttributeMaxDynamicSharedMemorySize, GEMM_SMEM);
    cudaFuncSetAttribute(attn_kernel,
                         cudaFuncAttributeMaxDynamicSharedMemorySize, ATT_SMEM);

    // 1) split inputs + weights
    conv_rows_kernel<<<dim3(1024, 3), 256>>>(q, k, v);
    conv_w_kernel<<<dim3(32, 32, 4), 256>>>(wq, wk, wv, wo);

    // 2) Q/K/V projections (Q pre-scaled by log2e/8; V -> single fp16 plane)
    gemm_kernel<<<dim3(8, 32, 3), 256, GEMM_SMEM>>>();

    // 3) tensor-core flash attention -> g_oh
    attn_kernel<<<dim3(16, 32), 256, ATT_SMEM>>>();

    // 4) output projection (fp16 2-term) -> fp32 out
    out_kernel<<<dim3(8, 32, 1), 256, GEMM_SMEM>>>(out);
}

// round 14
// speedup vs baseline: 1.3815x; 1.0552x over previous
#include <cuda_runtime.h>
#include <cuda_bf16.h>
#include <cuda_fp16.h>
#include <cstdint>

// ---------------------------------------------------------------------------
// Problem constants
// ---------------------------------------------------------------------------
#define BB 2
#define SS 2048
#define DD 1024
#define HH 16
#define RR 64
#define BH (BB * HH)   // 32
#define NEL (BB * SS * DD)

// ---------------------------------------------------------------------------
// mma.sync helpers (baseline PTX, plain sm_100 target)
// ---------------------------------------------------------------------------
__device__ __forceinline__ uint32_t smem_u32(const void* p) {
    uint32_t a;
    asm("{ .reg .u64 t; cvta.to.shared.u64 t, %1; cvt.u32.u64 %0, t; }"
        : "=r"(a) : "l"(p));
    return a;
}
__device__ __forceinline__ void ldm_x4(uint32_t* r, uint32_t addr) {
    asm volatile("ldmatrix.sync.aligned.m8n8.x4.shared.b16 {%0,%1,%2,%3}, [%4];"
                 : "=r"(r[0]), "=r"(r[1]), "=r"(r[2]), "=r"(r[3]) : "r"(addr));
}
__device__ __forceinline__ void ldm_x4_t(uint32_t* r, uint32_t addr) {
    asm volatile("ldmatrix.sync.aligned.m8n8.x4.trans.shared.b16 {%0,%1,%2,%3}, [%4];"
                 : "=r"(r[0]), "=r"(r[1]), "=r"(r[2]), "=r"(r[3]) : "r"(addr));
}
__device__ __forceinline__ void mma_bf16(float* c, const uint32_t* a,
                                         const uint32_t* b) {
    asm volatile(
        "mma.sync.aligned.m16n8k16.row.col.f32.bf16.bf16.f32 "
        "{%0,%1,%2,%3}, {%4,%5,%6,%7}, {%8,%9}, {%0,%1,%2,%3};"
        : "+f"(c[0]), "+f"(c[1]), "+f"(c[2]), "+f"(c[3])
        : "r"(a[0]), "r"(a[1]), "r"(a[2]), "r"(a[3]), "r"(b[0]), "r"(b[1]));
}
__device__ __forceinline__ void mma_f16(float* c, const uint32_t* a,
                                        const uint32_t* b) {
    asm volatile(
        "mma.sync.aligned.m16n8k16.row.col.f32.f16.f16.f32 "
        "{%0,%1,%2,%3}, {%4,%5,%6,%7}, {%8,%9}, {%0,%1,%2,%3};"
        : "+f"(c[0]), "+f"(c[1]), "+f"(c[2]), "+f"(c[3])
        : "r"(a[0]), "r"(a[1]), "r"(a[2]), "r"(a[3]), "r"(b[0]), "r"(b[1]));
}
__device__ __forceinline__ void cp16(uint32_t dst, const void* src) {
    asm volatile("cp.async.cg.shared.global [%0], [%1], 16;"
                 :: "r"(dst), "l"(__cvta_generic_to_global(src)));
}
#define CP_COMMIT() asm volatile("cp.async.commit_group;" ::: "memory")
#define CP_WAIT0()  asm volatile("cp.async.wait_group 0;" ::: "memory")

__device__ __forceinline__ uint32_t swz(uint32_t o) { return o ^ ((o >> 3) & 0x70); }

__device__ __forceinline__ float ex2f(float x) {
    float y;
    asm("ex2.approx.ftz.f32 %0, %1;" : "=f"(y) : "f"(x));
    return y;
}
__device__ __forceinline__ float rcpf(float x) {
    float y;
    asm("rcp.approx.ftz.f32 %0, %1;" : "=f"(y) : "f"(x));
    return y;
}

// Split a float pair into bf16 hi/lo packed u32s (rn rounding).
__device__ __forceinline__ void splitpair(float x, float y,
                                          uint32_t& h, uint32_t& l) {
    asm("cvt.rn.bf16x2.f32 %0, %1, %2;" : "=r"(h) : "f"(y), "f"(x));
    float hx = __uint_as_float(h << 16);
    float hy = __uint_as_float(h & 0xFFFF0000u);
    asm("cvt.rn.bf16x2.f32 %0, %1, %2;" : "=r"(l) : "f"(y - hy), "f"(x - hx));
}
__device__ __forceinline__ uint32_t packh2(float x, float y) {
    __half2 H = __floats2half2_rn(x, y);
    return *reinterpret_cast<uint32_t*>(&H);
}

// ---------------------------------------------------------------------------
// Scratch
// ---------------------------------------------------------------------------
__device__ __nv_bfloat16 g_qs[2][NEL];
__device__ __nv_bfloat16 g_ks[2][NEL];
__device__ __half        g_vh16[NEL];           // v input, single fp16 plane
__device__ __nv_bfloat16 g_wqT[2][DD * DD];
__device__ __nv_bfloat16 g_wkT[2][DD * DD];
__device__ __half        g_wvH[2][DD * DD];     // wv fp16 hi/lo, transposed
__device__ __half        g_woH[2][DD * DD];     // wo fp16 hi/lo, transposed
// projection outputs, [b,h,s,r] layout:
//   Q/K bf16 hi/lo planes (Q pre-scaled by 0.125*log2e, exp2 domain)
//   V  single fp16 plane
__device__ __nv_bfloat16 g_Qb[2][BH * SS * RR];
__device__ __nv_bfloat16 g_Kb[2][BH * SS * RR];
__device__ __half        g_Vh[BH * SS * RR];
// attention output, single fp16 plane, [z][s][r] == flat [4096][1024]
__device__ __half        g_oh[NEL];

// ---------------------------------------------------------------------------
// fp32 -> split converters. sel 0/1 (q,k): bf16 hi/lo. sel 2 (v): fp16 single.
// ---------------------------------------------------------------------------
__global__ void __launch_bounds__(256) conv_rows_kernel(
    const float* __restrict__ q, const float* __restrict__ k,
    const float* __restrict__ v)
{
    const int sel = blockIdx.y;
    const float* src = (sel == 0) ? q : (sel == 1) ? k : v;

    if (sel < 2) {
        __nv_bfloat16* d0 = (sel == 0) ? g_qs[0] : g_ks[0];
        __nv_bfloat16* d1 = (sel == 0) ? g_qs[1] : g_ks[1];
        for (int i = (blockIdx.x * blockDim.x + threadIdx.x) * 4; i < NEL;
             i += gridDim.x * blockDim.x * 4) {
            float4 x = *reinterpret_cast<const float4*>(src + i);
            uint32_t h0, l0, h1, l1;
            splitpair(x.x, x.y, h0, l0);
            splitpair(x.z, x.w, h1, l1);
            *reinterpret_cast<uint2*>(d0 + i) = make_uint2(h0, h1);
            *reinterpret_cast<uint2*>(d1 + i) = make_uint2(l0, l1);
        }
    } else {
        for (int i = (blockIdx.x * blockDim.x + threadIdx.x) * 4; i < NEL;
             i += gridDim.x * blockDim.x * 4) {
            float4 x = *reinterpret_cast<const float4*>(src + i);
            *reinterpret_cast<uint2*>(g_vh16 + i) =
                make_uint2(packh2(x.x, x.y), packh2(x.z, x.w));
        }
    }
}

// Weight transpose + split. sel 0/1: bf16 planes; sel 2 (wv) / 3 (wo): fp16.
__global__ void __launch_bounds__(256) conv_w_kernel(
    const float* __restrict__ wq, const float* __restrict__ wk,
    const float* __restrict__ wv, const float* __restrict__ wo)
{
    const int sel = blockIdx.z;
    const float* W = (sel == 0) ? wq : (sel == 1) ? wk : (sel == 2) ? wv : wo;

    __shared__ float tile[32][33];
    const int tx = threadIdx.x & 31;
    const int ty = threadIdx.x >> 5;
    const int ct = blockIdx.x;
    const int rt = blockIdx.y;

    #pragma unroll
    for (int i = 0; i < 4; i++) {
        const int d = rt * 32 + ty + i * 8;
        const int n = ct * 32 + tx;
        size_t idx;
        if (sel < 3) idx = ((size_t)(n >> 6) * DD + d) * RR + (n & 63);
        else         idx = (size_t)d * DD + n;
        tile[ty + i * 8][tx] = W[idx];
    }
    __syncthreads();
    #pragma unroll
    for (int i = 0; i < 4; i++) {
        const int nl = ty + i * 8;
        const int n  = ct * 32 + nl;
        const int d  = rt * 32 + tx;
        float x = tile[tx][nl];
        size_t o = (size_t)n * DD + d;
        if (sel < 2) {
            __nv_bfloat16* d0 = (sel == 0) ? g_wqT[0] : g_wkT[0];
            __nv_bfloat16* d1 = (sel == 0) ? g_wqT[1] : g_wkT[1];
            __nv_bfloat16 b0 = __float2bfloat16(x);
            d0[o] = b0;
            d1[o] = __float2bfloat16(x - __bfloat162float(b0));
        } else {
            __half* d0 = (sel == 2) ? g_wvH[0] : g_woH[0];
            __half* d1 = (sel == 2) ? g_wvH[1] : g_woH[1];
            __half h0 = __float2half_rn(x);
            d0[o] = h0;
            d1[o] = __float2half_rn(x - __half2float(h0));
        }
    }
}

// ---------------------------------------------------------------------------
// mma.sync split-bf16 GEMM for Q/K projections (48-stage, 3 terms).
// ---------------------------------------------------------------------------
#define GEMM_SMEM 65536

__global__ void __launch_bounds__(256) gemm_kernel()
{
    const int kind = blockIdx.z;           // 0 = Q, 1 = K
    const __nv_bfloat16 *Ax[2], *Bx[2];
    __nv_bfloat16 *P0, *P1;
    float scale = 1.0f;
    if (kind == 0) { Ax[0] = g_qs[0]; Ax[1] = g_qs[1];
                     Bx[0] = g_wqT[0]; Bx[1] = g_wqT[1];
                     P0 = g_Qb[0]; P1 = g_Qb[1];
                     scale = 0.125f * 1.4426950408889634f; }
    else           { Ax[0] = g_ks[0]; Ax[1] = g_ks[1];
                     Bx[0] = g_wkT[0]; Bx[1] = g_wkT[1];
                     P0 = g_Kb[0]; P1 = g_Kb[1]; }
    const int ti[3] = {0, 0, 1};
    const int tj[3] = {0, 1, 0};
    const int NST = 48;

    extern __shared__ char smem[];
    const uint32_t sb = smem_u32(smem);
    const int t      = threadIdx.x;
    const int lane   = t & 31;
    const int wid    = t >> 5;
    const int warp_m = wid >> 2;
    const int warp_n = wid & 3;
    const int m0 = blockIdx.y * 128;
    const int n0 = blockIdx.x * 128;

    float acc[4][4][4];
    #pragma unroll
    for (int a = 0; a < 4; a++)
        #pragma unroll
        for (int b = 0; b < 4; b++)
            #pragma unroll
            for (int c = 0; c < 4; c++) acc[a][b][c] = 0.f;

    const int a_row  = warp_m * 64 + (lane & 15);
    const int a_koff = (lane >> 4) * 16;
    const int b_row  = warp_n * 32 + (lane & 7) + ((lane >> 4) & 1) * 8;
    const int b_koff = ((lane >> 3) & 1) * 16;

    {
        const uint32_t abase = sb, bbase = sb + 16384;
        #pragma unroll
        for (int it = 0; it < 4; it++) {
            const int cid = it * 256 + t;
            const int row = cid >> 3, c16 = cid & 7;
            cp16(abase + swz(row * 128 + c16 * 16),
                 Ax[0] + (size_t)(m0 + row) * DD + c16 * 8);
            cp16(bbase + swz(row * 128 + c16 * 16),
                 Bx[0] + (size_t)(n0 + row) * DD + c16 * 8);
        }
        CP_COMMIT();
    }

    for (int s = 0; s < NST; s++) {
        CP_WAIT0();
        __syncthreads();
        if (s + 1 < NST) {
            const int sn = s + 1;
            const int tt = sn >> 4;
            const int k0 = (sn & 15) * 64;
            const __nv_bfloat16* Ag = Ax[ti[tt]];
            const __nv_bfloat16* Bg = Bx[tj[tt]];
            const uint32_t abase = sb + (sn & 1) * 32768;
            const uint32_t bbase = abase + 16384;
            #pragma unroll
            for (int it = 0; it < 4; it++) {
                const int cid = it * 256 + t;
                const int row = cid >> 3, c16 = cid & 7;
                cp16(abase + swz(row * 128 + c16 * 16),
                     Ag + (size_t)(m0 + row) * DD + k0 + c16 * 8);
                cp16(bbase + swz(row * 128 + c16 * 16),
                     Bg + (size_t)(n0 + row) * DD + k0 + c16 * 8);
            }
            CP_COMMIT();
        }
        const uint32_t abase = sb + (s & 1) * 32768;
        const uint32_t bbase = abase + 16384;
        #pragma unroll
        for (int k16 = 0; k16 < 64; k16 += 16) {
            uint32_t ar[4][4], br[4][2];
            #pragma unroll
            for (int mi = 0; mi < 4; mi++) {
                const int row = a_row + mi * 16;
                ldm_x4(ar[mi], abase + swz(row * 128 + k16 * 2 + a_koff));
            }
            #pragma unroll
            for (int nb = 0; nb < 2; nb++) {
                const int n = b_row + nb * 16;
                uint32_t r[4];
                ldm_x4(r, bbase + swz(n * 128 + k16 * 2 + b_koff));
                br[nb * 2][0] = r[0]; br[nb * 2][1] = r[1];
                br[nb * 2 + 1][0] = r[2]; br[nb * 2 + 1][1] = r[3];
            }
            #pragma unroll
            for (int mi = 0; mi < 4; mi++)
                #pragma unroll
                for (int ni = 0; ni < 4; ni++)
                    mma_bf16(acc[mi][ni], ar[mi], br[ni]);
        }
    }

    // epilogue -> bf16 hi/lo planes in [b,h,s,r]
    #pragma unroll
    for (int mi = 0; mi < 4; mi++) {
        #pragma unroll
        for (int ni = 0; ni < 4; ni++) {
            const int r0 = m0 + warp_m * 64 + mi * 16 + (lane >> 2);
            const int c  = n0 + warp_n * 32 + ni * 8 + (lane & 3) * 2;
            #pragma unroll
            for (int half = 0; half < 2; half++) {
                const int m = r0 + half * 8;
                float v0 = acc[mi][ni][half * 2] * scale;
                float v1 = acc[mi][ni][half * 2 + 1] * scale;
                const int h = c >> 6, r = c & 63;
                const int b = m >> 11, sl = m & 2047;
                size_t idx = (((size_t)b * HH + h) * SS + sl) * RR + r;
                uint32_t hh, ll;
                splitpair(v0, v1, hh, ll);
                *reinterpret_cast<uint32_t*>(&P0[idx]) = hh;
                *reinterpret_cast<uint32_t*>(&P1[idx]) = ll;
            }
        }
    }
}

// ---------------------------------------------------------------------------
// fp16 2-term GEMM (A single plane, B hi/lo planes, 32 stages).
//   kind 0: V projection  (A=g_vh16, B=g_wvH) -> g_Vh packed [b,h,s,r]
//   kind 1: out projection (A=g_oh,  B=g_woH) -> fp32 outC
// ---------------------------------------------------------------------------
__global__ void __launch_bounds__(256) f16gemm_kernel(float* __restrict__ outC,
                                                      int kind)
{
    const __half* Ag = (kind == 0) ? g_vh16 : g_oh;
    const __half* Bp[2] = {(kind == 0) ? g_wvH[0] : g_woH[0],
                           (kind == 0) ? g_wvH[1] : g_woH[1]};
    const int NST = 32;
    extern __shared__ char smem[];
    const uint32_t sb = smem_u32(smem);
    const int t      = threadIdx.x;
    const int lane   = t & 31;
    const int wid    = t >> 5;
    const int warp_m = wid >> 2;
    const int warp_n = wid & 3;
    const int m0 = blockIdx.y * 128;
    const int n0 = blockIdx.x * 128;

    float acc[4][4][4];
    #pragma unroll
    for (int a = 0; a < 4; a++)
        #pragma unroll
        for (int b = 0; b < 4; b++)
            #pragma unroll
            for (int c = 0; c < 4; c++) acc[a][b][c] = 0.f;

    const int a_row  = warp_m * 64 + (lane & 15);
    const int a_koff = (lane >> 4) * 16;
    const int b_row  = warp_n * 32 + (lane & 7) + ((lane >> 4) & 1) * 8;
    const int b_koff = ((lane >> 3) & 1) * 16;

    {
        const uint32_t abase = sb, bbase = sb + 16384;
        #pragma unroll
        for (int it = 0; it < 4; it++) {
            const int cid = it * 256 + t;
            const int row = cid >> 3, c16 = cid & 7;
            cp16(abase + swz(row * 128 + c16 * 16),
                 Ag + (size_t)(m0 + row) * DD + c16 * 8);
            cp16(bbase + swz(row * 128 + c16 * 16),
                 Bp[0] + (size_t)(n0 + row) * DD + c16 * 8);
        }
        CP_COMMIT();
    }

    for (int s = 0; s < NST; s++) {
        CP_WAIT0();
        __syncthreads();
        if (s + 1 < NST) {
            const int sn = s + 1;
            const int tt = sn >> 4;                 // B plane
            const int k0 = (sn & 15) * 64;
            const uint32_t abase = sb + (sn & 1) * 32768;
            const uint32_t bbase = abase + 16384;
            #pragma unroll
            for (int it = 0; it < 4; it++) {
                const int cid = it * 256 + t;
                const int row = cid >> 3, c16 = cid & 7;
                cp16(abase + swz(row * 128 + c16 * 16),
                     Ag + (size_t)(m0 + row) * DD + k0 + c16 * 8);
                cp16(bbase + swz(row * 128 + c16 * 16),
                     Bp[tt] + (size_t)(n0 + row) * DD + k0 + c16 * 8);
            }
            CP_COMMIT();
        }
        const uint32_t abase = sb + (s & 1) * 32768;
        const uint32_t bbase = abase + 16384;
        #pragma unroll
        for (int k16 = 0; k16 < 64; k16 += 16) {
            uint32_t ar[4][4], br[4][2];
            #pragma unroll
            for (int mi = 0; mi < 4; mi++) {
                const int row = a_row + mi * 16;
                ldm_x4(ar[mi], abase + swz(row * 128 + k16 * 2 + a_koff));
            }
            #pragma unroll
            for (int nb = 0; nb < 2; nb++) {
                const int n = b_row + nb * 16;
                uint32_t r[4];
                ldm_x4(r, bbase + swz(n * 128 + k16 * 2 + b_koff));
                br[nb * 2][0] = r[0]; br[nb * 2][1] = r[1];
                br[nb * 2 + 1][0] = r[2]; br[nb * 2 + 1][1] = r[3];
            }
            #pragma unroll
            for (int mi = 0; mi < 4; mi++)
                #pragma unroll
                for (int ni = 0; ni < 4; ni++)
                    mma_f16(acc[mi][ni], ar[mi], br[ni]);
        }
    }

    #pragma unroll
    for (int mi = 0; mi < 4; mi++) {
        #pragma unroll
        for (int ni = 0; ni < 4; ni++) {
            const int r0 = m0 + warp_m * 64 + mi * 16 + (lane >> 2);
            const int c  = n0 + warp_n * 32 + ni * 8 + (lane & 3) * 2;
            #pragma unroll
            for (int half = 0; half < 2; half++) {
                const int m = r0 + half * 8;
                float v0 = acc[mi][ni][half * 2];
                float v1 = acc[mi][ni][half * 2 + 1];
                if (kind == 0) {
                    const int h = c >> 6, r = c & 63;
                    const int b = m >> 11, sl = m & 2047;
                    size_t idx = (((size_t)b * HH + h) * SS + sl) * RR + r;
                    *reinterpret_cast<uint32_t*>(&g_Vh[idx]) = packh2(v0, v1);
                } else {
                    *reinterpret_cast<float2*>(&outC[(size_t)m * DD + c]) =
                        make_float2(v0, v1);
                }
            }
        }
    }
}

// ---------------------------------------------------------------------------
// Tensor-core flash attention (unchanged from the 510us version).
// ---------------------------------------------------------------------------
#define ATT_SMEM 81920

__global__ void __launch_bounds__(256, 2) attn_kernel()
{
    const int z  = blockIdx.y;
    const int s0 = blockIdx.x * 128;
    extern __shared__ char sm[];
    const uint32_t sb = smem_u32(sm);
    const int t = threadIdx.x, lane = t & 31, wid = t >> 5;
    const size_t zoff = (size_t)z * SS * RR;

    #define QOFF(p)      (sb + (p) * 16384u)
    #define KOFF(bf, p)  (sb + 32768u + (bf) * 24576u + (p) * 8192u)
    #define VOFF(bf)     (sb + 32768u + (bf) * 24576u + 16384u)

    #pragma unroll
    for (int p = 0; p < 2; p++) {
        const __nv_bfloat16* src = g_Qb[p] + zoff + (size_t)s0 * RR;
        #pragma unroll
        for (int it = 0; it < 4; it++) {
            const int cid = it * 256 + t;
            const int row = cid >> 3, c16 = cid & 7;
            cp16(QOFF(p) + swz(row * 128 + c16 * 16), src + row * 64 + c16 * 8);
        }
    }
    #pragma unroll
    for (int it = 0; it < 2; it++) {
        const int cid = it * 256 + t;
        const int row = cid >> 3, c16 = cid & 7;
        cp16(KOFF(0, 0) + swz(row * 128 + c16 * 16),
             g_Kb[0] + zoff + (size_t)row * RR + c16 * 8);
        cp16(KOFF(0, 1) + swz(row * 128 + c16 * 16),
             g_Kb[1] + zoff + (size_t)row * RR + c16 * 8);
        cp16(VOFF(0) + swz(row * 128 + c16 * 16),
             g_Vh + zoff + (size_t)row * RR + c16 * 8);
    }
    CP_COMMIT();

    float m0r = -3.0e38f, m1r = -3.0e38f, l0r = 0.f, l1r = 0.f;
    float oa[8][4];
    #pragma unroll
    for (int b = 0; b < 8; b++)
        #pragma unroll
        for (int c = 0; c < 4; c++) oa[b][c] = 0.f;

    for (int s = 0; s < 32; s++) {
        const int buf = s & 1;
        CP_WAIT0();
        __syncthreads();
        if (s + 1 < 32) {
            const int nb = (s + 1) & 1;
            const int kv = (s + 1) * 64;
            #pragma unroll
            for (int it = 0; it < 2; it++) {
                const int cid = it * 256 + t;
                const int row = cid >> 3, c16 = cid & 7;
                cp16(KOFF(nb, 0) + swz(row * 128 + c16 * 16),
                     g_Kb[0] + zoff + (size_t)(kv + row) * RR + c16 * 8);
                cp16(KOFF(nb, 1) + swz(row * 128 + c16 * 16),
                     g_Kb[1] + zoff + (size_t)(kv + row) * RR + c16 * 8);
                cp16(VOFF(nb) + swz(row * 128 + c16 * 16),
                     g_Vh + zoff + (size_t)(kv + row) * RR + c16 * 8);
            }
            CP_COMMIT();
        }

        // ---- GEMM1: S = Q K^T (bf16, 3 split terms) ----
        float sa[8][4];
        #pragma unroll
        for (int b = 0; b < 8; b++)
            #pragma unroll
            for (int c = 0; c < 4; c++) sa[b][c] = 0.f;

        #pragma unroll
        for (int kb = 0; kb < 4; kb++) {
            uint32_t aq[2][4];
            const int arow = wid * 16 + (lane & 15);
            const int akoff = kb * 32 + (lane >> 4) * 16;
            #pragma unroll
            for (int p = 0; p < 2; p++)
                ldm_x4(aq[p], QOFF(p) + swz(arow * 128 + akoff));
            #pragma unroll
            for (int g = 0; g < 4; g++) {
                uint32_t bk[2][4];
                const int brow = g * 16 + (lane & 7) + ((lane >> 4) & 1) * 8;
                const int bkoff = kb * 32 + ((lane >> 3) & 1) * 16;
                #pragma unroll
                for (int p = 0; p < 2; p++)
                    ldm_x4(bk[p], KOFF(buf, p) + swz(brow * 128 + bkoff));
                mma_bf16(sa[2 * g],     aq[0], &bk[0][0]);   // hi*hi
                mma_bf16(sa[2 * g + 1], aq[0], &bk[0][2]);
                mma_bf16(sa[2 * g],     aq[0], &bk[1][0]);   // hi*lo
                mma_bf16(sa[2 * g + 1], aq[0], &bk[1][2]);
                mma_bf16(sa[2 * g],     aq[1], &bk[0][0]);   // lo*hi
                mma_bf16(sa[2 * g + 1], aq[1], &bk[0][2]);
            }
        }

        // ---- online softmax (exp2 domain, MUFU ex2) ----
        float mt0 = -3.0e38f, mt1 = -3.0e38f;
        #pragma unroll
        for (int b = 0; b < 8; b++) {
            mt0 = fmaxf(mt0, fmaxf(sa[b][0], sa[b][1]));
            mt1 = fmaxf(mt1, fmaxf(sa[b][2], sa[b][3]));
        }
        mt0 = fmaxf(mt0, __shfl_xor_sync(0xffffffffu, mt0, 1));
        mt0 = fmaxf(mt0, __shfl_xor_sync(0xffffffffu, mt0, 2));
        mt1 = fmaxf(mt1, __shfl_xor_sync(0xffffffffu, mt1, 1));
        mt1 = fmaxf(mt1, __shfl_xor_sync(0xffffffffu, mt1, 2));
        const float mn0 = fmaxf(m0r, mt0), mn1 = fmaxf(m1r, mt1);
        const float al0 = ex2f(m0r - mn0), al1 = ex2f(m1r - mn1);
        m0r = mn0; m1r = mn1;
        float rs0 = 0.f, rs1 = 0.f;
        #pragma unroll
        for (int b = 0; b < 8; b++) {
            sa[b][0] = ex2f(sa[b][0] - mn0);
            sa[b][1] = ex2f(sa[b][1] - mn0);
            sa[b][2] = ex2f(sa[b][2] - mn1);
            sa[b][3] = ex2f(sa[b][3] - mn1);
            rs0 += sa[b][0] + sa[b][1];
            rs1 += sa[b][2] + sa[b][3];
        }
        rs0 += __shfl_xor_sync(0xffffffffu, rs0, 1);
        rs0 += __shfl_xor_sync(0xffffffffu, rs0, 2);
        rs1 += __shfl_xor_sync(0xffffffffu, rs1, 1);
        rs1 += __shfl_xor_sync(0xffffffffu, rs1, 2);
        l0r = l0r * al0 + rs0;
        l1r = l1r * al1 + rs1;
        #pragma unroll
        for (int b = 0; b < 8; b++) {
            oa[b][0] *= al0; oa[b][1] *= al0;
            oa[b][2] *= al1; oa[b][3] *= al1;
        }

        // ---- GEMM2: O += P V (fp16 P, single fp16 V) ----
        #pragma unroll
        for (int kb = 0; kb < 4; kb++) {
            uint32_t pp[4];
            pp[0] = packh2(sa[2 * kb][0],     sa[2 * kb][1]);
            pp[1] = packh2(sa[2 * kb][2],     sa[2 * kb][3]);
            pp[2] = packh2(sa[2 * kb + 1][0], sa[2 * kb + 1][1]);
            pp[3] = packh2(sa[2 * kb + 1][2], sa[2 * kb + 1][3]);
            #pragma unroll
            for (int g = 0; g < 4; g++) {
                uint32_t bv[4];
                const int trow = kb * 16 + (lane & 7) + ((lane >> 3) & 1) * 8;
                const int rbyte = g * 32 + ((lane >> 4) & 1) * 16;
                ldm_x4_t(bv, VOFF(buf) + swz(trow * 128 + rbyte));
                mma_f16(oa[2 * g],     pp, &bv[0]);
                mma_f16(oa[2 * g + 1], pp, &bv[2]);
            }
        }
    }

    // ---- epilogue: O/l -> g_oh single fp16 plane ----
    const float i0 = rcpf(l0r), i1 = rcpf(l1r);
    #pragma unroll
    for (int b = 0; b < 8; b++) {
        const int r   = b * 8 + (lane & 3) * 2;
        const int r0w = s0 + wid * 16 + (lane >> 2);
        size_t idx = zoff + (size_t)r0w * RR + r;
        *reinterpret_cast<uint32_t*>(&g_oh[idx]) =
            packh2(oa[b][0] * i0, oa[b][1] * i0);
        idx = zoff + (size_t)(r0w + 8) * RR + r;
        *reinterpret_cast<uint32_t*>(&g_oh[idx]) =
            packh2(oa[b][2] * i1, oa[b][3] * i1);
    }
    #undef QOFF
    #undef KOFF
    #undef VOFF
}

// ---------------------------------------------------------------------------
// Launch
// ---------------------------------------------------------------------------
extern "C" void kernel_launch(void* const* d_in, const int* in_sizes, int n_in,
                              void* d_out, int out_size)
{
    const float* q  = (const float*)d_in[0];
    const float* k  = (const float*)d_in[1];
    const float* v  = (const float*)d_in[2];
    const float* wq = (const float*)d_in[3];
    const float* wk = (const float*)d_in[4];
    const float* wv = (const float*)d_in[5];
    const float* wo = (const float*)d_in[6];
    float* out = (float*)d_out;

    (void)in_sizes; (void)n_in; (void)out_size;

    cudaFuncSetAttribute(gemm_kernel,
                         cudaFuncAttributeMaxDynamicSharedMemorySize, GEMM_SMEM);
    cudaFuncSetAttribute(f16gemm_kernel,
                         cudaFuncAttributeMaxDynamicSharedMemorySize, GEMM_SMEM);
    cudaFuncSetAttribute(attn_kernel,
                         cudaFuncAttributeMaxDynamicSharedMemorySize, ATT_SMEM);

    // 1) split inputs + weights
    conv_rows_kernel<<<dim3(1024, 3), 256>>>(q, k, v);
    conv_w_kernel<<<dim3(32, 32, 4), 256>>>(wq, wk, wv, wo);

    // 2) Q/K projections (bf16 3-term); V projection (fp16 2-term)
    gemm_kernel<<<dim3(8, 32, 2), 256, GEMM_SMEM>>>();
    f16gemm_kernel<<<dim3(8, 32, 1), 256, GEMM_SMEM>>>(nullptr, 0);

    // 3) tensor-core flash attention -> g_oh
    attn_kernel<<<dim3(16, 32), 256, ATT_SMEM>>>();

    // 4) output projection (fp16 2-term) -> fp32 out
    f16gemm_kernel<<<dim3(8, 32, 1), 256, GEMM_SMEM>>>(out, 1);
}